// round 1
// baseline (speedup 1.0000x reference)
#include <cuda_runtime.h>
#include <math.h>

#define B_  2
#define S_  2048
#define D_  1024
#define H_  16
#define HD  64

// ---------------- scratch (device globals: no allocation allowed) ----------------
__device__ float g_qkv[B_*S_*3*D_];        // [B,S,3D]
__device__ float g_q[B_*H_*S_*HD];         // [B,H,S,d]
__device__ float g_k[B_*H_*S_*HD];
__device__ float g_v[B_*H_*S_*HD];
__device__ float g_y[B_*S_*D_];            // attention out [B,S,D]
__device__ float g_cos[S_*32];
__device__ float g_sin[S_*32];

// ---------------- RoPE cos/sin table (fp64 angles -> fp32 table) ----------------
__global__ void rope_table_kernel() {
    int idx = blockIdx.x * 256 + threadIdx.x;     // S_*32 = 65536
    if (idx >= S_ * 32) return;
    int s = idx >> 5;
    int j = idx & 31;
    double inv = pow(10000.0, -((double)(2 * j)) / 64.0);
    double ang = (double)s * inv;
    g_cos[idx] = (float)cos(ang);
    g_sin[idx] = (float)sin(ang);
}

// ---------------- RoPE apply + [B,S,3D] -> [B,H,S,d] transpose ----------------
__global__ __launch_bounds__(256) void rope_kernel() {
    int idx = blockIdx.x * 256 + threadIdx.x;     // B_*S_*H_*HD = 4194304
    int i = idx & 63;
    int h = (idx >> 6) & 15;
    int s = (idx >> 10) & 2047;
    int b = idx >> 21;
    const float* row = g_qkv + (size_t)(b * S_ + s) * (3 * D_);
    int j = i & 31;
    float c  = g_cos[s * 32 + j];
    float sn = g_sin[s * 32 + j];
    float qv = row[h * 64 + i];
    float qp = row[h * 64 + (i ^ 32)];
    float kv = row[D_ + h * 64 + i];
    float kp = row[D_ + h * 64 + (i ^ 32)];
    float vv = row[2 * D_ + h * 64 + i];
    float sgn = (i < 32) ? -1.f : 1.f;
    float qo = qv * c + sgn * qp * sn;
    float ko = kv * c + sgn * kp * sn;
    size_t o = ((size_t)(b * H_ + h) * S_ + s) * HD + i;
    g_q[o] = qo;
    g_k[o] = ko;
    g_v[o] = vv;
}

// ---------------- fp32 SGEMM: C[M,N] = A[M,K] @ B[K,N] (row-major, tiles exact) ----------------
#define GBM 128
#define GBN 128
#define GBK 16
#define GTM 8
#define GTN 8
#define GST 132

__global__ __launch_bounds__(256) void sgemm_kernel(
    const float* __restrict__ A, const float* __restrict__ B, float* __restrict__ C,
    int M, int N, int K)
{
    __shared__ __align__(16) float As[GBK][GST];
    __shared__ __align__(16) float Bs[GBK][GST];
    const int tid  = threadIdx.x;
    const int tCol = tid & 15;
    const int tRow = tid >> 4;
    const int aRow = tid >> 2;
    const int aCol = (tid & 3) << 2;
    const int bRow = tid >> 5;
    const int bCol = (tid & 31) << 2;

    A += (size_t)blockIdx.y * GBM * K;
    B += blockIdx.x * GBN;
    C += (size_t)blockIdx.y * GBM * N + blockIdx.x * GBN;

    float acc[GTM][GTN];
    #pragma unroll
    for (int i = 0; i < GTM; i++)
        #pragma unroll
        for (int j = 0; j < GTN; j++) acc[i][j] = 0.f;

    for (int k0 = 0; k0 < K; k0 += GBK) {
        #pragma unroll
        for (int r = 0; r < GBM; r += 64) {
            float4 t = *(const float4*)(A + (size_t)(aRow + r) * K + aCol);
            As[aCol + 0][aRow + r] = t.x;
            As[aCol + 1][aRow + r] = t.y;
            As[aCol + 2][aRow + r] = t.z;
            As[aCol + 3][aRow + r] = t.w;
        }
        #pragma unroll
        for (int r = 0; r < GBK; r += 8) {
            *(float4*)&Bs[bRow + r][bCol] = *(const float4*)(B + (size_t)(bRow + r) * N + bCol);
        }
        __syncthreads();
        #pragma unroll
        for (int dot = 0; dot < GBK; dot++) {
            float regM[GTM], regN[GTN];
            *(float4*)&regM[0] = *(const float4*)&As[dot][tRow * GTM];
            *(float4*)&regM[4] = *(const float4*)&As[dot][tRow * GTM + 4];
            *(float4*)&regN[0] = *(const float4*)&Bs[dot][tCol * GTN];
            *(float4*)&regN[4] = *(const float4*)&Bs[dot][tCol * GTN + 4];
            #pragma unroll
            for (int i = 0; i < GTM; i++)
                #pragma unroll
                for (int j = 0; j < GTN; j++)
                    acc[i][j] = fmaf(regM[i], regN[j], acc[i][j]);
        }
        __syncthreads();
        A += GBK;
        B += (size_t)GBK * N;
    }
    #pragma unroll
    for (int i = 0; i < GTM; i++) {
        float* cr = C + (size_t)(tRow * GTM + i) * N + tCol * GTN;
        *(float4*)cr       = make_float4(acc[i][0], acc[i][1], acc[i][2], acc[i][3]);
        *(float4*)(cr + 4) = make_float4(acc[i][4], acc[i][5], acc[i][6], acc[i][7]);
    }
}

// ---------------- causal flash attention, fp32, 1 thread = 1 query ----------------
#define ABM 128
#define ABN 32

__global__ __launch_bounds__(128) void attn_kernel(const int* __restrict__ amask) {
    __shared__ __align__(16) float Ks[ABN][HD];
    __shared__ __align__(16) float Vs[ABN][HD];
    __shared__ float msk[ABN];
    const int tid = threadIdx.x;
    const int bh  = blockIdx.y;
    const int b   = bh >> 4;
    const int h   = bh & 15;
    const int qi  = blockIdx.x * ABM + tid;

    const float* qptr = g_q + ((size_t)bh * S_ + qi) * HD;
    float4 q[16];
    #pragma unroll
    for (int i = 0; i < 16; i++) {
        float4 t = *(const float4*)(qptr + i * 4);
        t.x *= 0.125f; t.y *= 0.125f; t.z *= 0.125f; t.w *= 0.125f;   // 1/sqrt(64)
        q[i] = t;
    }
    float4 o[16];
    #pragma unroll
    for (int i = 0; i < 16; i++) o[i] = make_float4(0.f, 0.f, 0.f, 0.f);
    float m = -INFINITY, l = 0.f;

    const float* kb = g_k + (size_t)bh * S_ * HD;
    const float* vb = g_v + (size_t)bh * S_ * HD;
    const int nkt = (blockIdx.x + 1) * (ABM / ABN);

    for (int kt = 0; kt < nkt; kt++) {
        __syncthreads();
        const float4* ks4 = (const float4*)(kb + (size_t)kt * ABN * HD);
        const float4* vs4 = (const float4*)(vb + (size_t)kt * ABN * HD);
        float4* Kd = (float4*)&Ks[0][0];
        float4* Vd = (float4*)&Vs[0][0];
        #pragma unroll
        for (int i = 0; i < 4; i++) {
            Kd[tid + i * 128] = ks4[tid + i * 128];
            Vd[tid + i * 128] = vs4[tid + i * 128];
        }
        if (tid < ABN)
            msk[tid] = (amask[b * S_ + kt * ABN + tid] == 0) ? -INFINITY : 0.f;
        __syncthreads();

        float s[ABN];
        #pragma unroll
        for (int j = 0; j < ABN; j++) s[j] = 0.f;
        #pragma unroll 4
        for (int dd = 0; dd < 16; dd++) {
            float4 qv = q[dd];
            #pragma unroll
            for (int j = 0; j < ABN; j++) {
                float4 kv = *(const float4*)&Ks[j][dd * 4];
                s[j] = fmaf(qv.x, kv.x, s[j]);
                s[j] = fmaf(qv.y, kv.y, s[j]);
                s[j] = fmaf(qv.z, kv.z, s[j]);
                s[j] = fmaf(qv.w, kv.w, s[j]);
            }
        }
        const int k0 = kt * ABN;
        float tmax = -INFINITY;
        #pragma unroll
        for (int j = 0; j < ABN; j++) {
            float sv = s[j] + msk[j];
            sv = (k0 + j <= qi) ? sv : -INFINITY;
            s[j] = sv;
            tmax = fmaxf(tmax, sv);
        }
        float mnew = fmaxf(m, tmax);
        float corr = __expf(m - mnew);
        m = mnew;
        l *= corr;
        #pragma unroll
        for (int i = 0; i < 16; i++) {
            o[i].x *= corr; o[i].y *= corr; o[i].z *= corr; o[i].w *= corr;
        }
        #pragma unroll
        for (int j = 0; j < ABN; j++) {
            float p = __expf(s[j] - mnew);
            l += p;
            s[j] = p;
        }
        #pragma unroll 4
        for (int j = 0; j < ABN; j++) {
            float p = s[j];
            #pragma unroll
            for (int dd = 0; dd < 16; dd++) {
                float4 vv = *(const float4*)&Vs[j][dd * 4];
                o[dd].x = fmaf(p, vv.x, o[dd].x);
                o[dd].y = fmaf(p, vv.y, o[dd].y);
                o[dd].z = fmaf(p, vv.z, o[dd].z);
                o[dd].w = fmaf(p, vv.w, o[dd].w);
            }
        }
    }

    float inv = 1.f / l;
    float* yp = g_y + (size_t)(b * S_ + qi) * D_ + h * HD;
    #pragma unroll
    for (int i = 0; i < 16; i++) {
        float4 t = o[i];
        t.x *= inv; t.y *= inv; t.z *= inv; t.w *= inv;
        *(float4*)(yp + i * 4) = t;
    }
}

// ---------------- launch ----------------
extern "C" void kernel_launch(void* const* d_in, const int* in_sizes, int n_in,
                              void* d_out, int out_size)
{
    const float* x     = (const float*)d_in[0];
    const float* w_qkv = (const float*)d_in[1];
    const float* w_o   = (const float*)d_in[2];
    const int*   amask = (const int*)d_in[3];
    float* out = (float*)d_out;

    float *qkv_p, *y_p;
    cudaGetSymbolAddress((void**)&qkv_p, g_qkv);
    cudaGetSymbolAddress((void**)&y_p,   g_y);

    rope_table_kernel<<<256, 256>>>();
    sgemm_kernel<<<dim3(3 * D_ / GBN, B_ * S_ / GBM), 256>>>(x, w_qkv, qkv_p,
                                                             B_ * S_, 3 * D_, D_);
    rope_kernel<<<(B_ * S_ * D_) / 256, 256>>>();
    attn_kernel<<<dim3(S_ / ABM, B_ * H_), 128>>>(amask);
    sgemm_kernel<<<dim3(D_ / GBN, B_ * S_ / GBM), 256>>>(y_p, w_o, out,
                                                          B_ * S_, D_, D_);
}

// round 2
// speedup vs baseline: 1.0637x; 1.0637x over previous
#include <cuda_runtime.h>
#include <math.h>
#include <stdint.h>

#define B_  2
#define S_  2048
#define D_  1024
#define H_  16
#define HD  64

// ---------------- scratch (device globals: no allocation allowed) ----------------
__device__ float g_qkv[B_*S_*3*D_];        // [B,S,3D]
__device__ float g_q[B_*H_*S_*HD];         // [B,H,S,d]
__device__ float g_k[B_*H_*S_*HD];
__device__ float g_v[B_*H_*S_*HD];
__device__ float g_y[B_*S_*D_];            // attention out [B,S,D]
__device__ float g_cos[S_*32];
__device__ float g_sin[S_*32];
// tf32 hi/lo splits
__device__ float g_xhi[B_*S_*D_];
__device__ float g_xlo[B_*S_*D_];
__device__ float g_wqh[D_*3*D_];
__device__ float g_wql[D_*3*D_];
__device__ float g_yhi[B_*S_*D_];
__device__ float g_ylo[B_*S_*D_];
__device__ float g_woh[D_*D_];
__device__ float g_wol[D_*D_];

// ---------------- RoPE cos/sin table (fp64 angles -> fp32 table) ----------------
__global__ void rope_table_kernel() {
    int idx = blockIdx.x * 256 + threadIdx.x;     // S_*32 = 65536
    if (idx >= S_ * 32) return;
    int s = idx >> 5;
    int j = idx & 31;
    double inv = pow(10000.0, -((double)(2 * j)) / 64.0);
    double ang = (double)s * inv;
    g_cos[idx] = (float)cos(ang);
    g_sin[idx] = (float)sin(ang);
}

// ---------------- tf32 hi/lo split ----------------
__global__ __launch_bounds__(256) void split_kernel(
    const float* __restrict__ src, float* __restrict__ hi, float* __restrict__ lo, int n)
{
    int i = blockIdx.x * 256 + threadIdx.x;
    if (i >= n) return;
    float v = src[i];
    float h;
    asm("cvt.rna.tf32.f32 %0, %1;" : "=f"(h) : "f"(v));
    float l = v - h;
    asm("cvt.rna.tf32.f32 %0, %1;" : "=f"(l) : "f"(l));
    hi[i] = h;
    lo[i] = l;
}

// ---------------- RoPE apply + [B,S,3D] -> [B,H,S,d] transpose ----------------
__global__ __launch_bounds__(256) void rope_kernel() {
    int idx = blockIdx.x * 256 + threadIdx.x;     // B_*S_*H_*HD = 4194304
    int i = idx & 63;
    int h = (idx >> 6) & 15;
    int s = (idx >> 10) & 2047;
    int b = idx >> 21;
    const float* row = g_qkv + (size_t)(b * S_ + s) * (3 * D_);
    int j = i & 31;
    float c  = g_cos[s * 32 + j];
    float sn = g_sin[s * 32 + j];
    float qv = row[h * 64 + i];
    float qp = row[h * 64 + (i ^ 32)];
    float kv = row[D_ + h * 64 + i];
    float kp = row[D_ + h * 64 + (i ^ 32)];
    float vv = row[2 * D_ + h * 64 + i];
    float sgn = (i < 32) ? -1.f : 1.f;
    float qo = qv * c + sgn * qp * sn;
    float ko = kv * c + sgn * kp * sn;
    size_t o = ((size_t)(b * H_ + h) * S_ + s) * HD + i;
    g_q[o] = qo;
    g_k[o] = ko;
    g_v[o] = vv;
}

// ---------------- 3xTF32 tensor-core GEMM: C[M,N] = A[M,K] @ B[K,N] ----------------
// A split (hi/lo) row-major, B split row-major. Block 128x128x32, 256 thr, warp 32x64.
#define TBM 128
#define TBN 128
#define TBK 32
// smem float offsets
#define SA_PAD 36         // 32 + 4
#define SB_PAD 132        // 128 + 4
#define OFF_AH 0
#define OFF_AL (128*SA_PAD)
#define OFF_BH (2*128*SA_PAD)
#define OFF_BL (2*128*SA_PAD + 32*SB_PAD)
#define SMEM_GEMM_FLOATS (2*128*SA_PAD + 2*32*SB_PAD)

__device__ __forceinline__ void mma_tf32(float* d, const uint32_t* a, const uint32_t* b) {
    asm volatile(
        "mma.sync.aligned.m16n8k8.row.col.f32.tf32.tf32.f32 "
        "{%0,%1,%2,%3}, {%4,%5,%6,%7}, {%8,%9}, {%0,%1,%2,%3};\n"
        : "+f"(d[0]), "+f"(d[1]), "+f"(d[2]), "+f"(d[3])
        : "r"(a[0]), "r"(a[1]), "r"(a[2]), "r"(a[3]), "r"(b[0]), "r"(b[1]));
}

__global__ __launch_bounds__(256, 2) void tf32_gemm_kernel(
    const float* __restrict__ Ahi, const float* __restrict__ Alo,
    const float* __restrict__ Bhi, const float* __restrict__ Blo,
    float* __restrict__ C, int M, int N, int K)
{
    extern __shared__ float sm[];
    float* sAhi = sm + OFF_AH;   // [128][SA_PAD]  (m-major, k contig)
    float* sAlo = sm + OFF_AL;
    float* sBhi = sm + OFF_BH;   // [32][SB_PAD]   (k-major, n contig)
    float* sBlo = sm + OFF_BL;

    const int tid  = threadIdx.x;
    const int warp = tid >> 5;
    const int lane = tid & 31;
    const int g = lane >> 2;
    const int t = lane & 3;
    const int mBase = (warp >> 1) * 32;   // warp M origin
    const int nBase = (warp & 1) * 64;    // warp N origin

    const float* Agh = Ahi + (size_t)blockIdx.y * TBM * K;
    const float* Agl = Alo + (size_t)blockIdx.y * TBM * K;
    const float* Bgh = Bhi + blockIdx.x * TBN;
    const float* Bgl = Blo + blockIdx.x * TBN;

    float acc[2][8][4];
    #pragma unroll
    for (int mt = 0; mt < 2; mt++)
        #pragma unroll
        for (int nt = 0; nt < 8; nt++)
            #pragma unroll
            for (int r = 0; r < 4; r++) acc[mt][nt][r] = 0.f;

    const int aR = tid >> 3;            // 0..31
    const int aC = (tid & 7) << 2;      // 0..28 step 4
    const int bR = tid >> 5;            // 0..7
    const int bC = (tid & 31) << 2;     // 0..124 step 4

    for (int k0 = 0; k0 < K; k0 += TBK) {
        // load A tile (128 x 32) hi/lo
        #pragma unroll
        for (int r = 0; r < 128; r += 32) {
            const size_t ga = (size_t)(aR + r) * K + k0 + aC;
            float4 h4 = *(const float4*)(Agh + ga);
            float4 l4 = *(const float4*)(Agl + ga);
            *(float4*)&sAhi[(aR + r) * SA_PAD + aC] = h4;
            *(float4*)&sAlo[(aR + r) * SA_PAD + aC] = l4;
        }
        // load B tile (32 x 128) hi/lo
        #pragma unroll
        for (int r = 0; r < 32; r += 8) {
            const size_t gb = (size_t)(k0 + bR + r) * N + bC;
            float4 h4 = *(const float4*)(Bgh + gb);
            float4 l4 = *(const float4*)(Bgl + gb);
            *(float4*)&sBhi[(bR + r) * SB_PAD + bC] = h4;
            *(float4*)&sBlo[(bR + r) * SB_PAD + bC] = l4;
        }
        __syncthreads();

        const uint32_t* ph = (const uint32_t*)sAhi;
        const uint32_t* pl = (const uint32_t*)sAlo;
        const uint32_t* qh = (const uint32_t*)sBhi;
        const uint32_t* ql = (const uint32_t*)sBlo;

        #pragma unroll
        for (int kk = 0; kk < 4; kk++) {
            const int k8 = kk * 8;
            uint32_t ah[2][4], al[2][4];
            #pragma unroll
            for (int mt = 0; mt < 2; mt++) {
                const int base = (mBase + mt * 16 + g) * SA_PAD + k8 + t;
                ah[mt][0] = ph[base];
                ah[mt][1] = ph[base + 8 * SA_PAD];
                ah[mt][2] = ph[base + 4];
                ah[mt][3] = ph[base + 8 * SA_PAD + 4];
                al[mt][0] = pl[base];
                al[mt][1] = pl[base + 8 * SA_PAD];
                al[mt][2] = pl[base + 4];
                al[mt][3] = pl[base + 8 * SA_PAD + 4];
            }
            #pragma unroll
            for (int nt = 0; nt < 8; nt++) {
                const int bbase = (k8 + t) * SB_PAD + nBase + nt * 8 + g;
                uint32_t bh[2], bl[2];
                bh[0] = qh[bbase];
                bh[1] = qh[bbase + 4 * SB_PAD];
                bl[0] = ql[bbase];
                bl[1] = ql[bbase + 4 * SB_PAD];
                #pragma unroll
                for (int mt = 0; mt < 2; mt++) {
                    mma_tf32(acc[mt][nt], ah[mt], bh);
                    mma_tf32(acc[mt][nt], ah[mt], bl);
                    mma_tf32(acc[mt][nt], al[mt], bh);
                }
            }
        }
        __syncthreads();
    }

    // epilogue
    C += (size_t)blockIdx.y * TBM * N + blockIdx.x * TBN;
    #pragma unroll
    for (int mt = 0; mt < 2; mt++) {
        const int r0 = mBase + mt * 16 + g;
        #pragma unroll
        for (int nt = 0; nt < 8; nt++) {
            const int c = nBase + nt * 8 + t * 2;
            *(float2*)&C[(size_t)r0 * N + c]       = make_float2(acc[mt][nt][0], acc[mt][nt][1]);
            *(float2*)&C[(size_t)(r0 + 8) * N + c] = make_float2(acc[mt][nt][2], acc[mt][nt][3]);
        }
    }
}

// ---------------- causal flash attention, fp32, 1 thread = 1 query ----------------
#define ABM 128
#define ABN 32

__global__ __launch_bounds__(128) void attn_kernel(const int* __restrict__ amask) {
    __shared__ __align__(16) float Ks[ABN][HD];
    __shared__ __align__(16) float Vs[ABN][HD];
    __shared__ float msk[ABN];
    const int tid = threadIdx.x;
    const int bh  = blockIdx.y;
    const int b   = bh >> 4;
    const int h   = bh & 15;
    const int qi  = blockIdx.x * ABM + tid;

    const float* qptr = g_q + ((size_t)bh * S_ + qi) * HD;
    float4 q[16];
    #pragma unroll
    for (int i = 0; i < 16; i++) {
        float4 tq = *(const float4*)(qptr + i * 4);
        tq.x *= 0.125f; tq.y *= 0.125f; tq.z *= 0.125f; tq.w *= 0.125f;   // 1/sqrt(64)
        q[i] = tq;
    }
    float4 o[16];
    #pragma unroll
    for (int i = 0; i < 16; i++) o[i] = make_float4(0.f, 0.f, 0.f, 0.f);
    float m = -INFINITY, l = 0.f;

    const float* kb = g_k + (size_t)bh * S_ * HD;
    const float* vb = g_v + (size_t)bh * S_ * HD;
    const int nkt = (blockIdx.x + 1) * (ABM / ABN);

    for (int kt = 0; kt < nkt; kt++) {
        __syncthreads();
        const float4* ks4 = (const float4*)(kb + (size_t)kt * ABN * HD);
        const float4* vs4 = (const float4*)(vb + (size_t)kt * ABN * HD);
        float4* Kd = (float4*)&Ks[0][0];
        float4* Vd = (float4*)&Vs[0][0];
        #pragma unroll
        for (int i = 0; i < 4; i++) {
            Kd[tid + i * 128] = ks4[tid + i * 128];
            Vd[tid + i * 128] = vs4[tid + i * 128];
        }
        if (tid < ABN)
            msk[tid] = (amask[b * S_ + kt * ABN + tid] == 0) ? -INFINITY : 0.f;
        __syncthreads();

        float s[ABN];
        #pragma unroll
        for (int j = 0; j < ABN; j++) s[j] = 0.f;
        #pragma unroll 4
        for (int dd = 0; dd < 16; dd++) {
            float4 qv = q[dd];
            #pragma unroll
            for (int j = 0; j < ABN; j++) {
                float4 kv = *(const float4*)&Ks[j][dd * 4];
                s[j] = fmaf(qv.x, kv.x, s[j]);
                s[j] = fmaf(qv.y, kv.y, s[j]);
                s[j] = fmaf(qv.z, kv.z, s[j]);
                s[j] = fmaf(qv.w, kv.w, s[j]);
            }
        }
        const int k0 = kt * ABN;
        float tmax = -INFINITY;
        #pragma unroll
        for (int j = 0; j < ABN; j++) {
            float sv = s[j] + msk[j];
            sv = (k0 + j <= qi) ? sv : -INFINITY;
            s[j] = sv;
            tmax = fmaxf(tmax, sv);
        }
        float mnew = fmaxf(m, tmax);
        float corr = __expf(m - mnew);
        m = mnew;
        l *= corr;
        #pragma unroll
        for (int i = 0; i < 16; i++) {
            o[i].x *= corr; o[i].y *= corr; o[i].z *= corr; o[i].w *= corr;
        }
        #pragma unroll
        for (int j = 0; j < ABN; j++) {
            float p = __expf(s[j] - mnew);
            l += p;
            s[j] = p;
        }
        #pragma unroll 4
        for (int j = 0; j < ABN; j++) {
            float p = s[j];
            #pragma unroll
            for (int dd = 0; dd < 16; dd++) {
                float4 vv = *(const float4*)&Vs[j][dd * 4];
                o[dd].x = fmaf(p, vv.x, o[dd].x);
                o[dd].y = fmaf(p, vv.y, o[dd].y);
                o[dd].z = fmaf(p, vv.z, o[dd].z);
                o[dd].w = fmaf(p, vv.w, o[dd].w);
            }
        }
    }

    float inv = 1.f / l;
    float* yp = g_y + (size_t)(b * S_ + qi) * D_ + h * HD;
    #pragma unroll
    for (int i = 0; i < 16; i++) {
        float4 tv = o[i];
        tv.x *= inv; tv.y *= inv; tv.z *= inv; tv.w *= inv;
        *(float4*)(yp + i * 4) = tv;
    }
}

// ---------------- launch ----------------
extern "C" void kernel_launch(void* const* d_in, const int* in_sizes, int n_in,
                              void* d_out, int out_size)
{
    const float* x     = (const float*)d_in[0];
    const float* w_qkv = (const float*)d_in[1];
    const float* w_o   = (const float*)d_in[2];
    const int*   amask = (const int*)d_in[3];
    float* out = (float*)d_out;

    float *qkv_p, *y_p;
    float *xhi, *xlo, *wqh, *wql, *yhi, *ylo, *woh, *wol;
    cudaGetSymbolAddress((void**)&qkv_p, g_qkv);
    cudaGetSymbolAddress((void**)&y_p,   g_y);
    cudaGetSymbolAddress((void**)&xhi, g_xhi);
    cudaGetSymbolAddress((void**)&xlo, g_xlo);
    cudaGetSymbolAddress((void**)&wqh, g_wqh);
    cudaGetSymbolAddress((void**)&wql, g_wql);
    cudaGetSymbolAddress((void**)&yhi, g_yhi);
    cudaGetSymbolAddress((void**)&ylo, g_ylo);
    cudaGetSymbolAddress((void**)&woh, g_woh);
    cudaGetSymbolAddress((void**)&wol, g_wol);

    const int smem_gemm = SMEM_GEMM_FLOATS * 4;
    cudaFuncSetAttribute(tf32_gemm_kernel,
                         cudaFuncAttributeMaxDynamicSharedMemorySize, smem_gemm);

    rope_table_kernel<<<256, 256>>>();

    // split inputs for QKV gemm
    split_kernel<<<(B_*S_*D_ + 255) / 256, 256>>>(x, xhi, xlo, B_*S_*D_);
    split_kernel<<<(D_*3*D_ + 255) / 256, 256>>>(w_qkv, wqh, wql, D_*3*D_);

    // QKV = x @ w_qkv : [4096,1024] @ [1024,3072]
    tf32_gemm_kernel<<<dim3(3*D_/TBN, B_*S_/TBM), 256, smem_gemm>>>(
        xhi, xlo, wqh, wql, qkv_p, B_*S_, 3*D_, D_);

    rope_kernel<<<(B_*S_*D_) / 256, 256>>>();
    attn_kernel<<<dim3(S_/ABM, B_*H_), 128>>>(amask);

    // split attention output + w_o for O-proj gemm
    split_kernel<<<(B_*S_*D_ + 255) / 256, 256>>>(y_p, yhi, ylo, B_*S_*D_);
    split_kernel<<<(D_*D_ + 255) / 256, 256>>>(w_o, woh, wol, D_*D_);

    // out = y @ w_o : [4096,1024] @ [1024,1024]
    tf32_gemm_kernel<<<dim3(D_/TBN, B_*S_/TBM), 256, smem_gemm>>>(
        yhi, ylo, woh, wol, out, B_*S_, D_, D_);
}

// round 3
// speedup vs baseline: 1.5018x; 1.4118x over previous
#include <cuda_runtime.h>
#include <math.h>
#include <stdint.h>

#define B_  2
#define S_  2048
#define D_  1024
#define H_  16
#define HD  64

// ---------------- scratch (device globals: no allocation allowed) ----------------
__device__ float g_qkv[B_*S_*3*D_];        // [B,S,3D]
__device__ float g_cos[S_*32];
__device__ float g_sin[S_*32];
// tf32 hi/lo splits
__device__ float g_xhi[B_*S_*D_];
__device__ float g_xlo[B_*S_*D_];
__device__ float g_wqh[D_*3*D_];
__device__ float g_wql[D_*3*D_];
__device__ float g_woh[D_*D_];
__device__ float g_wol[D_*D_];
// attention operands, [B,H,S,d] hi/lo (scale folded into q)
__device__ float g_qhi[B_*H_*S_*HD];
__device__ float g_qlo[B_*H_*S_*HD];
__device__ float g_khi[B_*H_*S_*HD];
__device__ float g_klo[B_*H_*S_*HD];
__device__ float g_vhi[B_*H_*S_*HD];
__device__ float g_vlo[B_*H_*S_*HD];
// attention output splits [B,S,D]
__device__ float g_yhi[B_*S_*D_];
__device__ float g_ylo[B_*S_*D_];

__device__ __forceinline__ float to_tf32(float v) {
    float r;
    asm("cvt.rna.tf32.f32 %0, %1;" : "=f"(r) : "f"(v));
    return r;
}

// ---------------- RoPE cos/sin table (fp64 angles -> fp32 table) ----------------
__global__ void rope_table_kernel() {
    int idx = blockIdx.x * 256 + threadIdx.x;     // S_*32 = 65536
    if (idx >= S_ * 32) return;
    int s = idx >> 5;
    int j = idx & 31;
    double inv = pow(10000.0, -((double)(2 * j)) / 64.0);
    double ang = (double)s * inv;
    g_cos[idx] = (float)cos(ang);
    g_sin[idx] = (float)sin(ang);
}

// ---------------- tf32 hi/lo split ----------------
__global__ __launch_bounds__(256) void split_kernel(
    const float* __restrict__ src, float* __restrict__ hi, float* __restrict__ lo, int n)
{
    int i = blockIdx.x * 256 + threadIdx.x;
    if (i >= n) return;
    float v = src[i];
    float h = to_tf32(v);
    float l = to_tf32(v - h);
    hi[i] = h;
    lo[i] = l;
}

// ---------------- RoPE apply + transpose + tf32 split (scale folded into q) ----------------
__global__ __launch_bounds__(256) void rope_split_kernel() {
    int idx = blockIdx.x * 256 + threadIdx.x;     // B_*S_*H_*HD = 4194304
    int i = idx & 63;
    int h = (idx >> 6) & 15;
    int s = (idx >> 10) & 2047;
    int b = idx >> 21;
    const float* row = g_qkv + (size_t)(b * S_ + s) * (3 * D_);
    int j = i & 31;
    float c  = g_cos[s * 32 + j];
    float sn = g_sin[s * 32 + j];
    float qv = row[h * 64 + i];
    float qp = row[h * 64 + (i ^ 32)];
    float kv = row[D_ + h * 64 + i];
    float kp = row[D_ + h * 64 + (i ^ 32)];
    float vv = row[2 * D_ + h * 64 + i];
    float sgn = (i < 32) ? -1.f : 1.f;
    float qo = (qv * c + sgn * qp * sn) * 0.125f;   // fold 1/sqrt(64)
    float ko = kv * c + sgn * kp * sn;
    size_t o = ((size_t)(b * H_ + h) * S_ + s) * HD + i;
    float qh = to_tf32(qo); g_qhi[o] = qh; g_qlo[o] = to_tf32(qo - qh);
    float kh = to_tf32(ko); g_khi[o] = kh; g_klo[o] = to_tf32(ko - kh);
    float vh = to_tf32(vv); g_vhi[o] = vh; g_vlo[o] = to_tf32(vv - vh);
}

// ---------------- mma helper ----------------
__device__ __forceinline__ void mma_tf32(float* d, const uint32_t* a, const uint32_t* b) {
    asm volatile(
        "mma.sync.aligned.m16n8k8.row.col.f32.tf32.tf32.f32 "
        "{%0,%1,%2,%3}, {%4,%5,%6,%7}, {%8,%9}, {%0,%1,%2,%3};\n"
        : "+f"(d[0]), "+f"(d[1]), "+f"(d[2]), "+f"(d[3])
        : "r"(a[0]), "r"(a[1]), "r"(a[2]), "r"(a[3]), "r"(b[0]), "r"(b[1]));
}

// ---------------- 3xTF32 tensor-core GEMM: C[M,N] = A[M,K] @ B[K,N] ----------------
#define TBM 128
#define TBN 128
#define TBK 32
#define SA_PAD 36
#define SB_PAD 132
#define OFF_AH 0
#define OFF_AL (128*SA_PAD)
#define OFF_BH (2*128*SA_PAD)
#define OFF_BL (2*128*SA_PAD + 32*SB_PAD)
#define SMEM_GEMM_FLOATS (2*128*SA_PAD + 2*32*SB_PAD)

__global__ __launch_bounds__(256, 2) void tf32_gemm_kernel(
    const float* __restrict__ Ahi, const float* __restrict__ Alo,
    const float* __restrict__ Bhi, const float* __restrict__ Blo,
    float* __restrict__ C, int M, int N, int K)
{
    extern __shared__ float sm[];
    float* sAhi = sm + OFF_AH;
    float* sAlo = sm + OFF_AL;
    float* sBhi = sm + OFF_BH;
    float* sBlo = sm + OFF_BL;

    const int tid  = threadIdx.x;
    const int warp = tid >> 5;
    const int lane = tid & 31;
    const int g = lane >> 2;
    const int t = lane & 3;
    const int mBase = (warp >> 1) * 32;
    const int nBase = (warp & 1) * 64;

    const float* Agh = Ahi + (size_t)blockIdx.y * TBM * K;
    const float* Agl = Alo + (size_t)blockIdx.y * TBM * K;
    const float* Bgh = Bhi + blockIdx.x * TBN;
    const float* Bgl = Blo + blockIdx.x * TBN;

    float acc[2][8][4];
    #pragma unroll
    for (int mt = 0; mt < 2; mt++)
        #pragma unroll
        for (int nt = 0; nt < 8; nt++)
            #pragma unroll
            for (int r = 0; r < 4; r++) acc[mt][nt][r] = 0.f;

    const int aR = tid >> 3;
    const int aC = (tid & 7) << 2;
    const int bR = tid >> 5;
    const int bC = (tid & 31) << 2;

    for (int k0 = 0; k0 < K; k0 += TBK) {
        #pragma unroll
        for (int r = 0; r < 128; r += 32) {
            const size_t ga = (size_t)(aR + r) * K + k0 + aC;
            *(float4*)&sAhi[(aR + r) * SA_PAD + aC] = *(const float4*)(Agh + ga);
            *(float4*)&sAlo[(aR + r) * SA_PAD + aC] = *(const float4*)(Agl + ga);
        }
        #pragma unroll
        for (int r = 0; r < 32; r += 8) {
            const size_t gb = (size_t)(k0 + bR + r) * N + bC;
            *(float4*)&sBhi[(bR + r) * SB_PAD + bC] = *(const float4*)(Bgh + gb);
            *(float4*)&sBlo[(bR + r) * SB_PAD + bC] = *(const float4*)(Bgl + gb);
        }
        __syncthreads();

        const uint32_t* ph = (const uint32_t*)sAhi;
        const uint32_t* pl = (const uint32_t*)sAlo;
        const uint32_t* qh = (const uint32_t*)sBhi;
        const uint32_t* ql = (const uint32_t*)sBlo;

        #pragma unroll
        for (int kk = 0; kk < 4; kk++) {
            const int k8 = kk * 8;
            uint32_t ah[2][4], al[2][4];
            #pragma unroll
            for (int mt = 0; mt < 2; mt++) {
                const int base = (mBase + mt * 16 + g) * SA_PAD + k8 + t;
                ah[mt][0] = ph[base];
                ah[mt][1] = ph[base + 8 * SA_PAD];
                ah[mt][2] = ph[base + 4];
                ah[mt][3] = ph[base + 8 * SA_PAD + 4];
                al[mt][0] = pl[base];
                al[mt][1] = pl[base + 8 * SA_PAD];
                al[mt][2] = pl[base + 4];
                al[mt][3] = pl[base + 8 * SA_PAD + 4];
            }
            #pragma unroll
            for (int nt = 0; nt < 8; nt++) {
                const int bbase = (k8 + t) * SB_PAD + nBase + nt * 8 + g;
                uint32_t bh2[2], bl2[2];
                bh2[0] = qh[bbase];
                bh2[1] = qh[bbase + 4 * SB_PAD];
                bl2[0] = ql[bbase];
                bl2[1] = ql[bbase + 4 * SB_PAD];
                #pragma unroll
                for (int mt = 0; mt < 2; mt++) {
                    mma_tf32(acc[mt][nt], ah[mt], bh2);
                    mma_tf32(acc[mt][nt], ah[mt], bl2);
                    mma_tf32(acc[mt][nt], al[mt], bh2);
                }
            }
        }
        __syncthreads();
    }

    C += (size_t)blockIdx.y * TBM * N + blockIdx.x * TBN;
    #pragma unroll
    for (int mt = 0; mt < 2; mt++) {
        const int r0 = mBase + mt * 16 + g;
        #pragma unroll
        for (int nt = 0; nt < 8; nt++) {
            const int c = nBase + nt * 8 + t * 2;
            *(float2*)&C[(size_t)r0 * N + c]       = make_float2(acc[mt][nt][0], acc[mt][nt][1]);
            *(float2*)&C[(size_t)(r0 + 8) * N + c] = make_float2(acc[mt][nt][2], acc[mt][nt][3]);
        }
    }
}

// ---------------- tensor-core causal flash attention (3xTF32) ----------------
#define AQ   128      // q rows per block
#define AK   64       // keys per tile
#define APAD 68

// smem float offsets
#define A_QH 0
#define A_QL (A_QH + 128*APAD)
#define A_PH (A_QL + 128*APAD)
#define A_PL (A_PH + 128*APAD)
#define A_KH (A_PL + 128*APAD)
#define A_KL (A_KH + 64*APAD)
#define A_VH (A_KL + 64*APAD)
#define A_VL (A_VH + 64*APAD)
#define A_MS (A_VL + 64*APAD)
#define SMEM_ATTN_FLOATS (A_MS + 64)

__global__ __launch_bounds__(256, 1) void attn_tc_kernel(const int* __restrict__ amask) {
    extern __shared__ float sma[];
    float* sQh = sma + A_QH;
    float* sQl = sma + A_QL;
    float* sPh = sma + A_PH;
    float* sPl = sma + A_PL;
    float* sKh = sma + A_KH;
    float* sKl = sma + A_KL;
    float* sVh = sma + A_VH;
    float* sVl = sma + A_VL;
    float* sM  = sma + A_MS;

    const int tid  = threadIdx.x;
    const int warp = tid >> 5;
    const int lane = tid & 31;
    const int g = lane >> 2;
    const int t = lane & 3;
    const int bh = blockIdx.y;
    const int b  = bh >> 4;
    const int h  = bh & 15;
    const int qbase = blockIdx.x * AQ;
    const int wrow  = warp * 16;

    // load Q tile (128 x 64) hi/lo
    {
        const float* qh = g_qhi + ((size_t)bh * S_ + qbase) * HD;
        const float* ql = g_qlo + ((size_t)bh * S_ + qbase) * HD;
        for (int i = tid; i < 2048; i += 256) {
            int r = i >> 4, c = (i & 15) << 2;
            *(float4*)&sQh[r * APAD + c] = *(const float4*)(qh + r * HD + c);
            *(float4*)&sQl[r * APAD + c] = *(const float4*)(ql + r * HD + c);
        }
    }

    float oacc[8][4];
    #pragma unroll
    for (int nt = 0; nt < 8; nt++)
        #pragma unroll
        for (int r = 0; r < 4; r++) oacc[nt][r] = 0.f;
    float mrun[2] = {-INFINITY, -INFINITY};
    float lrun[2] = {0.f, 0.f};

    const float* kh = g_khi + (size_t)bh * S_ * HD;
    const float* kl = g_klo + (size_t)bh * S_ * HD;
    const float* vh = g_vhi + (size_t)bh * S_ * HD;
    const float* vl = g_vlo + (size_t)bh * S_ * HD;

    const int nkt = (qbase + AQ) / AK;

    for (int kt = 0; kt < nkt; kt++) {
        __syncthreads();
        const size_t koff = (size_t)kt * AK * HD;
        for (int i = tid; i < 1024; i += 256) {
            int r = i >> 4, c = (i & 15) << 2;
            *(float4*)&sKh[r * APAD + c] = *(const float4*)(kh + koff + r * HD + c);
            *(float4*)&sKl[r * APAD + c] = *(const float4*)(kl + koff + r * HD + c);
            *(float4*)&sVh[r * APAD + c] = *(const float4*)(vh + koff + r * HD + c);
            *(float4*)&sVl[r * APAD + c] = *(const float4*)(vl + koff + r * HD + c);
        }
        if (tid < 64)
            sM[tid] = (amask[b * S_ + kt * AK + tid] == 0) ? -INFINITY : 0.f;
        __syncthreads();

        // warp fully above the diagonal for this tile -> skip
        if (kt * AK > qbase + wrow + 15) continue;

        const uint32_t* pQh = (const uint32_t*)sQh;
        const uint32_t* pQl = (const uint32_t*)sQl;
        const uint32_t* pKh = (const uint32_t*)sKh;
        const uint32_t* pKl = (const uint32_t*)sKl;

        // ---- S = Q K^T ----
        float sacc[8][4];
        #pragma unroll
        for (int nt = 0; nt < 8; nt++)
            #pragma unroll
            for (int r = 0; r < 4; r++) sacc[nt][r] = 0.f;

        #pragma unroll
        for (int ks = 0; ks < 8; ks++) {
            uint32_t ah[4], al[4];
            const int abase = (wrow + g) * APAD + ks * 8 + t;
            ah[0] = pQh[abase];             al[0] = pQl[abase];
            ah[1] = pQh[abase + 8 * APAD];  al[1] = pQl[abase + 8 * APAD];
            ah[2] = pQh[abase + 4];         al[2] = pQl[abase + 4];
            ah[3] = pQh[abase + 8 * APAD + 4]; al[3] = pQl[abase + 8 * APAD + 4];
            #pragma unroll
            for (int nt = 0; nt < 8; nt++) {
                const int bbase = (nt * 8 + g) * APAD + ks * 8 + t;
                uint32_t bh2[2], bl2[2];
                bh2[0] = pKh[bbase];      bh2[1] = pKh[bbase + 4];
                bl2[0] = pKl[bbase];      bl2[1] = pKl[bbase + 4];
                mma_tf32(sacc[nt], ah, bh2);
                mma_tf32(sacc[nt], ah, bl2);
                mma_tf32(sacc[nt], al, bh2);
            }
        }

        // ---- masks + row max ----
        const bool diag = (kt * AK + AK - 1) > (qbase + wrow);
        float tmax[2] = {-INFINITY, -INFINITY};
        #pragma unroll
        for (int nt = 0; nt < 8; nt++) {
            #pragma unroll
            for (int e = 0; e < 4; e++) {
                const int colL = nt * 8 + t * 2 + (e & 1);
                float v = sacc[nt][e] + sM[colL];
                if (diag) {
                    const int row = qbase + wrow + g + ((e >> 1) << 3);
                    const int col = kt * AK + colL;
                    if (col > row) v = -INFINITY;
                }
                sacc[nt][e] = v;
                tmax[e >> 1] = fmaxf(tmax[e >> 1], v);
            }
        }
        #pragma unroll
        for (int i = 0; i < 2; i++) {
            tmax[i] = fmaxf(tmax[i], __shfl_xor_sync(0xffffffff, tmax[i], 1));
            tmax[i] = fmaxf(tmax[i], __shfl_xor_sync(0xffffffff, tmax[i], 2));
        }

        // ---- online softmax update ----
        float corr[2], psum[2] = {0.f, 0.f};
        #pragma unroll
        for (int i = 0; i < 2; i++) {
            float mnew = fmaxf(mrun[i], tmax[i]);
            corr[i] = __expf(mrun[i] - mnew);
            mrun[i] = mnew;
            lrun[i] *= corr[i];
        }
        #pragma unroll
        for (int nt = 0; nt < 8; nt++) {
            oacc[nt][0] *= corr[0]; oacc[nt][1] *= corr[0];
            oacc[nt][2] *= corr[1]; oacc[nt][3] *= corr[1];
        }
        // p = exp(s - m), split, store to sP
        #pragma unroll
        for (int nt = 0; nt < 8; nt++) {
            #pragma unroll
            for (int half = 0; half < 2; half++) {
                float p0 = __expf(sacc[nt][half * 2 + 0] - mrun[half]);
                float p1 = __expf(sacc[nt][half * 2 + 1] - mrun[half]);
                psum[half] += p0 + p1;
                float h0 = to_tf32(p0), h1 = to_tf32(p1);
                const int row = wrow + g + half * 8;
                const int col = nt * 8 + t * 2;
                *(float2*)&sPh[row * APAD + col] = make_float2(h0, h1);
                *(float2*)&sPl[row * APAD + col] = make_float2(to_tf32(p0 - h0), to_tf32(p1 - h1));
            }
        }
        #pragma unroll
        for (int i = 0; i < 2; i++) {
            psum[i] += __shfl_xor_sync(0xffffffff, psum[i], 1);
            psum[i] += __shfl_xor_sync(0xffffffff, psum[i], 2);
            lrun[i] += psum[i];
        }
        __syncwarp();

        // ---- O += P V ----
        const uint32_t* pPh = (const uint32_t*)sPh;
        const uint32_t* pPl = (const uint32_t*)sPl;
        const uint32_t* pVh = (const uint32_t*)sVh;
        const uint32_t* pVl = (const uint32_t*)sVl;
        #pragma unroll
        for (int ks = 0; ks < 8; ks++) {
            uint32_t ah[4], al[4];
            const int abase = (wrow + g) * APAD + ks * 8 + t;
            ah[0] = pPh[abase];                al[0] = pPl[abase];
            ah[1] = pPh[abase + 8 * APAD];     al[1] = pPl[abase + 8 * APAD];
            ah[2] = pPh[abase + 4];            al[2] = pPl[abase + 4];
            ah[3] = pPh[abase + 8 * APAD + 4]; al[3] = pPl[abase + 8 * APAD + 4];
            #pragma unroll
            for (int nt = 0; nt < 8; nt++) {
                const int bbase = (ks * 8 + t) * APAD + nt * 8 + g;
                uint32_t bh2[2], bl2[2];
                bh2[0] = pVh[bbase];  bh2[1] = pVh[bbase + 4 * APAD];
                bl2[0] = pVl[bbase];  bl2[1] = pVl[bbase + 4 * APAD];
                mma_tf32(oacc[nt], ah, bh2);
                mma_tf32(oacc[nt], ah, bl2);
                mma_tf32(oacc[nt], al, bh2);
            }
        }
        __syncwarp();
    }

    // ---- epilogue: o/l, split, write y hi/lo ----
    const float inv0 = 1.f / lrun[0];
    const float inv1 = 1.f / lrun[1];
    const int r0 = qbase + wrow + g;
    const int r1 = r0 + 8;
    #pragma unroll
    for (int nt = 0; nt < 8; nt++) {
        const int col = h * HD + nt * 8 + t * 2;
        float v0 = oacc[nt][0] * inv0, v1 = oacc[nt][1] * inv0;
        float v2 = oacc[nt][2] * inv1, v3 = oacc[nt][3] * inv1;
        float h0 = to_tf32(v0), h1 = to_tf32(v1), h2 = to_tf32(v2), h3 = to_tf32(v3);
        size_t o0 = (size_t)(b * S_ + r0) * D_ + col;
        size_t o1 = (size_t)(b * S_ + r1) * D_ + col;
        *(float2*)&g_yhi[o0] = make_float2(h0, h1);
        *(float2*)&g_ylo[o0] = make_float2(to_tf32(v0 - h0), to_tf32(v1 - h1));
        *(float2*)&g_yhi[o1] = make_float2(h2, h3);
        *(float2*)&g_ylo[o1] = make_float2(to_tf32(v2 - h2), to_tf32(v3 - h3));
    }
}

// ---------------- launch ----------------
extern "C" void kernel_launch(void* const* d_in, const int* in_sizes, int n_in,
                              void* d_out, int out_size)
{
    const float* x     = (const float*)d_in[0];
    const float* w_qkv = (const float*)d_in[1];
    const float* w_o   = (const float*)d_in[2];
    const int*   amask = (const int*)d_in[3];
    float* out = (float*)d_out;

    float *qkv_p;
    float *xhi, *xlo, *wqh, *wql, *yhi, *ylo, *woh, *wol;
    cudaGetSymbolAddress((void**)&qkv_p, g_qkv);
    cudaGetSymbolAddress((void**)&xhi, g_xhi);
    cudaGetSymbolAddress((void**)&xlo, g_xlo);
    cudaGetSymbolAddress((void**)&wqh, g_wqh);
    cudaGetSymbolAddress((void**)&wql, g_wql);
    cudaGetSymbolAddress((void**)&yhi, g_yhi);
    cudaGetSymbolAddress((void**)&ylo, g_ylo);
    cudaGetSymbolAddress((void**)&woh, g_woh);
    cudaGetSymbolAddress((void**)&wol, g_wol);

    const int smem_gemm = SMEM_GEMM_FLOATS * 4;
    cudaFuncSetAttribute(tf32_gemm_kernel,
                         cudaFuncAttributeMaxDynamicSharedMemorySize, smem_gemm);
    const int smem_attn = SMEM_ATTN_FLOATS * 4;
    cudaFuncSetAttribute(attn_tc_kernel,
                         cudaFuncAttributeMaxDynamicSharedMemorySize, smem_attn);

    rope_table_kernel<<<256, 256>>>();

    split_kernel<<<(B_*S_*D_ + 255) / 256, 256>>>(x, xhi, xlo, B_*S_*D_);
    split_kernel<<<(D_*3*D_ + 255) / 256, 256>>>(w_qkv, wqh, wql, D_*3*D_);
    split_kernel<<<(D_*D_ + 255) / 256, 256>>>(w_o, woh, wol, D_*D_);

    // QKV = x @ w_qkv : [4096,1024] @ [1024,3072]
    tf32_gemm_kernel<<<dim3(3*D_/TBN, B_*S_/TBM), 256, smem_gemm>>>(
        xhi, xlo, wqh, wql, qkv_p, B_*S_, 3*D_, D_);

    rope_split_kernel<<<(B_*S_*D_) / 256, 256>>>();

    attn_tc_kernel<<<dim3(S_/AQ, B_*H_), 256, smem_attn>>>(amask);

    // out = y @ w_o : [4096,1024] @ [1024,1024]
    tf32_gemm_kernel<<<dim3(D_/TBN, B_*S_/TBM), 256, smem_gemm>>>(
        yhi, ylo, woh, wol, out, B_*S_, D_, D_);
}

// round 4
// speedup vs baseline: 1.6204x; 1.0790x over previous
#include <cuda_runtime.h>
#include <math.h>
#include <stdint.h>

#define B_  2
#define S_  2048
#define D_  1024
#define H_  16
#define HD  64

// ---------------- scratch (device globals: no allocation allowed) ----------------
__device__ float g_qkv[B_*S_*3*D_];        // [B,S,3D]
__device__ float g_cos[S_*32];
__device__ float g_sin[S_*32];
// tf32 hi/lo splits
__device__ float g_xhi[B_*S_*D_];
__device__ float g_xlo[B_*S_*D_];
__device__ float g_wqh[D_*3*D_];
__device__ float g_wql[D_*3*D_];
__device__ float g_woh[D_*D_];
__device__ float g_wol[D_*D_];
// attention operands, [B,H,S,d] hi/lo (scale folded into q)
__device__ float g_qhi[B_*H_*S_*HD];
__device__ float g_qlo[B_*H_*S_*HD];
__device__ float g_khi[B_*H_*S_*HD];
__device__ float g_klo[B_*H_*S_*HD];
__device__ float g_vhi[B_*H_*S_*HD];
__device__ float g_vlo[B_*H_*S_*HD];
// attention output splits [B,S,D]
__device__ float g_yhi[B_*S_*D_];
__device__ float g_ylo[B_*S_*D_];

__device__ __forceinline__ float to_tf32(float v) {
    float r;
    asm("cvt.rna.tf32.f32 %0, %1;" : "=f"(r) : "f"(v));
    return r;
}

__device__ __forceinline__ void cp16(float* dst, const float* src) {
    uint32_t d = (uint32_t)__cvta_generic_to_shared(dst);
    asm volatile("cp.async.cg.shared.global [%0], [%1], 16;\n" :: "r"(d), "l"(src));
}
__device__ __forceinline__ void cp_commit() {
    asm volatile("cp.async.commit_group;\n");
}
template<int N> __device__ __forceinline__ void cp_wait() {
    asm volatile("cp.async.wait_group %0;\n" :: "n"(N));
}

// ---------------- RoPE cos/sin table (fp64 angles -> fp32 table) ----------------
__global__ void rope_table_kernel() {
    int idx = blockIdx.x * 256 + threadIdx.x;     // S_*32 = 65536
    if (idx >= S_ * 32) return;
    int s = idx >> 5;
    int j = idx & 31;
    double inv = pow(10000.0, -((double)(2 * j)) / 64.0);
    double ang = (double)s * inv;
    g_cos[idx] = (float)cos(ang);
    g_sin[idx] = (float)sin(ang);
}

// ---------------- tf32 hi/lo split ----------------
__global__ __launch_bounds__(256) void split_kernel(
    const float* __restrict__ src, float* __restrict__ hi, float* __restrict__ lo, int n)
{
    int i = blockIdx.x * 256 + threadIdx.x;
    if (i >= n) return;
    float v = src[i];
    float h = to_tf32(v);
    float l = to_tf32(v - h);
    hi[i] = h;
    lo[i] = l;
}

// ---------------- RoPE apply + transpose + tf32 split (scale folded into q) ----------------
__global__ __launch_bounds__(256) void rope_split_kernel() {
    int idx = blockIdx.x * 256 + threadIdx.x;     // B_*S_*H_*HD = 4194304
    int i = idx & 63;
    int h = (idx >> 6) & 15;
    int s = (idx >> 10) & 2047;
    int b = idx >> 21;
    const float* row = g_qkv + (size_t)(b * S_ + s) * (3 * D_);
    int j = i & 31;
    float c  = g_cos[s * 32 + j];
    float sn = g_sin[s * 32 + j];
    float qv = row[h * 64 + i];
    float qp = row[h * 64 + (i ^ 32)];
    float kv = row[D_ + h * 64 + i];
    float kp = row[D_ + h * 64 + (i ^ 32)];
    float vv = row[2 * D_ + h * 64 + i];
    float sgn = (i < 32) ? -1.f : 1.f;
    float qo = (qv * c + sgn * qp * sn) * 0.125f;   // fold 1/sqrt(64)
    float ko = kv * c + sgn * kp * sn;
    size_t o = ((size_t)(b * H_ + h) * S_ + s) * HD + i;
    float qh = to_tf32(qo); g_qhi[o] = qh; g_qlo[o] = to_tf32(qo - qh);
    float kh = to_tf32(ko); g_khi[o] = kh; g_klo[o] = to_tf32(ko - kh);
    float vh = to_tf32(vv); g_vhi[o] = vh; g_vlo[o] = to_tf32(vv - vh);
}

// ---------------- mma helper ----------------
__device__ __forceinline__ void mma_tf32(float* d, const uint32_t* a, const uint32_t* b) {
    asm volatile(
        "mma.sync.aligned.m16n8k8.row.col.f32.tf32.tf32.f32 "
        "{%0,%1,%2,%3}, {%4,%5,%6,%7}, {%8,%9}, {%0,%1,%2,%3};\n"
        : "+f"(d[0]), "+f"(d[1]), "+f"(d[2]), "+f"(d[3])
        : "r"(a[0]), "r"(a[1]), "r"(a[2]), "r"(a[3]), "r"(b[0]), "r"(b[1]));
}

// ---------------- 3xTF32 tensor-core GEMM, 2-stage cp.async pipeline ----------------
#define TBM 128
#define TBN 128
#define TBK 32
#define SA_PAD 36
#define SB_PAD 132
// one stage layout (floats)
#define G_AH 0
#define G_AL (128*SA_PAD)
#define G_BH (2*128*SA_PAD)
#define G_BL (2*128*SA_PAD + 32*SB_PAD)
#define G_STAGE (2*128*SA_PAD + 2*32*SB_PAD)
#define SMEM_GEMM_FLOATS (2*G_STAGE)

__device__ __forceinline__ void gemm_stage_load(
    float* st, const float* Agh, const float* Agl,
    const float* Bgh, const float* Bgl, int k0, int tid, int K, int N)
{
    const int aR = tid >> 3;
    const int aC = (tid & 7) << 2;
    #pragma unroll
    for (int r = 0; r < 128; r += 32) {
        const size_t ga = (size_t)(aR + r) * K + k0 + aC;
        cp16(&st[G_AH + (aR + r) * SA_PAD + aC], Agh + ga);
        cp16(&st[G_AL + (aR + r) * SA_PAD + aC], Agl + ga);
    }
    const int bR = tid >> 5;
    const int bC = (tid & 31) << 2;
    #pragma unroll
    for (int r = 0; r < 32; r += 8) {
        const size_t gb = (size_t)(k0 + bR + r) * N + bC;
        cp16(&st[G_BH + (bR + r) * SB_PAD + bC], Bgh + gb);
        cp16(&st[G_BL + (bR + r) * SB_PAD + bC], Bgl + gb);
    }
}

__global__ __launch_bounds__(256, 1) void tf32_gemm_kernel(
    const float* __restrict__ Ahi, const float* __restrict__ Alo,
    const float* __restrict__ Bhi, const float* __restrict__ Blo,
    float* __restrict__ C, int M, int N, int K)
{
    extern __shared__ float sm[];

    const int tid  = threadIdx.x;
    const int warp = tid >> 5;
    const int lane = tid & 31;
    const int g = lane >> 2;
    const int t = lane & 3;
    const int mBase = (warp >> 1) * 32;
    const int nBase = (warp & 1) * 64;

    const float* Agh = Ahi + (size_t)blockIdx.y * TBM * K;
    const float* Agl = Alo + (size_t)blockIdx.y * TBM * K;
    const float* Bgh = Bhi + blockIdx.x * TBN;
    const float* Bgl = Blo + blockIdx.x * TBN;

    float acc[2][8][4];
    #pragma unroll
    for (int mt = 0; mt < 2; mt++)
        #pragma unroll
        for (int nt = 0; nt < 8; nt++)
            #pragma unroll
            for (int r = 0; r < 4; r++) acc[mt][nt][r] = 0.f;

    const int NT = K / TBK;
    gemm_stage_load(sm, Agh, Agl, Bgh, Bgl, 0, tid, K, N);
    cp_commit();

    for (int it = 0; it < NT; it++) {
        if (it + 1 < NT) {
            gemm_stage_load(sm + ((it + 1) & 1) * G_STAGE, Agh, Agl, Bgh, Bgl,
                            (it + 1) * TBK, tid, K, N);
            cp_commit();
            cp_wait<1>();
        } else {
            cp_wait<0>();
        }
        __syncthreads();

        float* st = sm + (it & 1) * G_STAGE;
        const uint32_t* ph = (const uint32_t*)(st + G_AH);
        const uint32_t* pl = (const uint32_t*)(st + G_AL);
        const uint32_t* qh = (const uint32_t*)(st + G_BH);
        const uint32_t* ql = (const uint32_t*)(st + G_BL);

        #pragma unroll
        for (int kk = 0; kk < 4; kk++) {
            const int k8 = kk * 8;
            uint32_t ah[2][4], al[2][4];
            #pragma unroll
            for (int mt = 0; mt < 2; mt++) {
                const int base = (mBase + mt * 16 + g) * SA_PAD + k8 + t;
                ah[mt][0] = ph[base];
                ah[mt][1] = ph[base + 8 * SA_PAD];
                ah[mt][2] = ph[base + 4];
                ah[mt][3] = ph[base + 8 * SA_PAD + 4];
                al[mt][0] = pl[base];
                al[mt][1] = pl[base + 8 * SA_PAD];
                al[mt][2] = pl[base + 4];
                al[mt][3] = pl[base + 8 * SA_PAD + 4];
            }
            #pragma unroll
            for (int nt = 0; nt < 8; nt++) {
                const int bbase = (k8 + t) * SB_PAD + nBase + nt * 8 + g;
                uint32_t bh2[2], bl2[2];
                bh2[0] = qh[bbase];
                bh2[1] = qh[bbase + 4 * SB_PAD];
                bl2[0] = ql[bbase];
                bl2[1] = ql[bbase + 4 * SB_PAD];
                #pragma unroll
                for (int mt = 0; mt < 2; mt++) {
                    mma_tf32(acc[mt][nt], ah[mt], bh2);
                    mma_tf32(acc[mt][nt], ah[mt], bl2);
                    mma_tf32(acc[mt][nt], al[mt], bh2);
                }
            }
        }
        __syncthreads();
    }

    C += (size_t)blockIdx.y * TBM * N + blockIdx.x * TBN;
    #pragma unroll
    for (int mt = 0; mt < 2; mt++) {
        const int r0 = mBase + mt * 16 + g;
        #pragma unroll
        for (int nt = 0; nt < 8; nt++) {
            const int c = nBase + nt * 8 + t * 2;
            *(float2*)&C[(size_t)r0 * N + c]       = make_float2(acc[mt][nt][0], acc[mt][nt][1]);
            *(float2*)&C[(size_t)(r0 + 8) * N + c] = make_float2(acc[mt][nt][2], acc[mt][nt][3]);
        }
    }
}

// ---------------- tensor-core causal flash attention (3xTF32, Q-in-regs, cp.async KV) ----------------
#define AQ   128
#define AK   64
#define APAD 68

// smem float offsets
#define A_PH 0
#define A_PL (128*APAD)
#define A_KV (2*128*APAD)
#define KV_ARR (64*APAD)
#define KV_STAGE (4*KV_ARR)
#define A_MSK (A_KV + 2*KV_STAGE)
#define SMEM_ATTN_FLOATS (A_MSK + S_)

__device__ __forceinline__ void attn_stage_load(
    float* sma, int st, const float* kh, const float* kl,
    const float* vh, const float* vl, size_t koff, int tid)
{
    float* base = sma + A_KV + st * KV_STAGE;
    #pragma unroll
    for (int i = tid; i < 1024; i += 256) {
        int r = i >> 4, c = (i & 15) << 2;
        const size_t gsrc = koff + (size_t)r * HD + c;
        const int sdst = r * APAD + c;
        cp16(&base[0 * KV_ARR + sdst], kh + gsrc);
        cp16(&base[1 * KV_ARR + sdst], kl + gsrc);
        cp16(&base[2 * KV_ARR + sdst], vh + gsrc);
        cp16(&base[3 * KV_ARR + sdst], vl + gsrc);
    }
}

__global__ __launch_bounds__(256, 1) void attn_tc_kernel(const int* __restrict__ amask) {
    extern __shared__ float sma[];
    float* sPh = sma + A_PH;
    float* sPl = sma + A_PL;
    float* sMf = sma + A_MSK;

    const int tid  = threadIdx.x;
    const int warp = tid >> 5;
    const int lane = tid & 31;
    const int g = lane >> 2;
    const int t = lane & 3;
    const int bh = blockIdx.y;
    const int b  = bh >> 4;
    const int h  = bh & 15;
    const int qbase = blockIdx.x * AQ;
    const int wrow  = warp * 16;

    const float* kh = g_khi + (size_t)bh * S_ * HD;
    const float* kl = g_klo + (size_t)bh * S_ * HD;
    const float* vh = g_vhi + (size_t)bh * S_ * HD;
    const float* vl = g_vlo + (size_t)bh * S_ * HD;

    const int nkt = (qbase + AQ) / AK;

    // prefetch tile 0
    attn_stage_load(sma, 0, kh, kl, vh, vl, 0, tid);
    cp_commit();

    // stage Q through the P buffers, then read frags into registers
    {
        const float* qhp = g_qhi + ((size_t)bh * S_ + qbase) * HD;
        const float* qlp = g_qlo + ((size_t)bh * S_ + qbase) * HD;
        for (int i = tid; i < 2048; i += 256) {
            int r = i >> 4, c = (i & 15) << 2;
            *(float4*)&sPh[r * APAD + c] = *(const float4*)(qhp + r * HD + c);
            *(float4*)&sPl[r * APAD + c] = *(const float4*)(qlp + r * HD + c);
        }
        // attention-mask row -> float once per block
        for (int i = tid; i < S_; i += 256)
            sMf[i] = (amask[b * S_ + i] == 0) ? -INFINITY : 0.f;
    }
    __syncthreads();

    uint32_t Qh[8][4], Ql[8][4];
    {
        const uint32_t* pQh = (const uint32_t*)sPh;
        const uint32_t* pQl = (const uint32_t*)sPl;
        #pragma unroll
        for (int ks = 0; ks < 8; ks++) {
            const int abase = (wrow + g) * APAD + ks * 8 + t;
            Qh[ks][0] = pQh[abase];                Ql[ks][0] = pQl[abase];
            Qh[ks][1] = pQh[abase + 8 * APAD];     Ql[ks][1] = pQl[abase + 8 * APAD];
            Qh[ks][2] = pQh[abase + 4];            Ql[ks][2] = pQl[abase + 4];
            Qh[ks][3] = pQh[abase + 8 * APAD + 4]; Ql[ks][3] = pQl[abase + 8 * APAD + 4];
        }
    }
    // each warp henceforth touches only its own 16 rows of sP -> no block sync needed here

    float oacc[8][4];
    #pragma unroll
    for (int nt = 0; nt < 8; nt++)
        #pragma unroll
        for (int r = 0; r < 4; r++) oacc[nt][r] = 0.f;
    float mrun[2] = {-INFINITY, -INFINITY};
    float lrun[2] = {0.f, 0.f};

    for (int kt = 0; kt < nkt; kt++) {
        if (kt + 1 < nkt) {
            attn_stage_load(sma, (kt + 1) & 1, kh, kl, vh, vl,
                            (size_t)(kt + 1) * AK * HD, tid);
            cp_commit();
            cp_wait<1>();
        } else {
            cp_wait<0>();
        }
        __syncthreads();

        const bool skip = (kt * AK > qbase + wrow + 15);
        if (!skip) {
            float* stg = sma + A_KV + (kt & 1) * KV_STAGE;
            const uint32_t* pKh = (const uint32_t*)(stg + 0 * KV_ARR);
            const uint32_t* pKl = (const uint32_t*)(stg + 1 * KV_ARR);
            const uint32_t* pVh = (const uint32_t*)(stg + 2 * KV_ARR);
            const uint32_t* pVl = (const uint32_t*)(stg + 3 * KV_ARR);

            // ---- S = Q K^T ----
            float sacc[8][4];
            #pragma unroll
            for (int nt = 0; nt < 8; nt++)
                #pragma unroll
                for (int r = 0; r < 4; r++) sacc[nt][r] = 0.f;

            #pragma unroll
            for (int ks = 0; ks < 8; ks++) {
                #pragma unroll
                for (int nt = 0; nt < 8; nt++) {
                    const int bbase = (nt * 8 + g) * APAD + ks * 8 + t;
                    uint32_t bh2[2], bl2[2];
                    bh2[0] = pKh[bbase];      bh2[1] = pKh[bbase + 4];
                    bl2[0] = pKl[bbase];      bl2[1] = pKl[bbase + 4];
                    mma_tf32(sacc[nt], Qh[ks], bh2);
                    mma_tf32(sacc[nt], Qh[ks], bl2);
                    mma_tf32(sacc[nt], Ql[ks], bh2);
                }
            }

            // ---- masks + row max ----
            const bool diag = (kt * AK + AK - 1) > (qbase + wrow);
            float tmax[2] = {-INFINITY, -INFINITY};
            #pragma unroll
            for (int nt = 0; nt < 8; nt++) {
                #pragma unroll
                for (int e = 0; e < 4; e++) {
                    const int colL = nt * 8 + t * 2 + (e & 1);
                    float v = sacc[nt][e] + sMf[kt * AK + colL];
                    if (diag) {
                        const int row = qbase + wrow + g + ((e >> 1) << 3);
                        const int col = kt * AK + colL;
                        if (col > row) v = -INFINITY;
                    }
                    sacc[nt][e] = v;
                    tmax[e >> 1] = fmaxf(tmax[e >> 1], v);
                }
            }
            #pragma unroll
            for (int i = 0; i < 2; i++) {
                tmax[i] = fmaxf(tmax[i], __shfl_xor_sync(0xffffffff, tmax[i], 1));
                tmax[i] = fmaxf(tmax[i], __shfl_xor_sync(0xffffffff, tmax[i], 2));
            }

            // ---- online softmax update ----
            float corr[2], psum[2] = {0.f, 0.f};
            #pragma unroll
            for (int i = 0; i < 2; i++) {
                float mnew = fmaxf(mrun[i], tmax[i]);
                corr[i] = __expf(mrun[i] - mnew);
                mrun[i] = mnew;
                lrun[i] *= corr[i];
            }
            #pragma unroll
            for (int nt = 0; nt < 8; nt++) {
                oacc[nt][0] *= corr[0]; oacc[nt][1] *= corr[0];
                oacc[nt][2] *= corr[1]; oacc[nt][3] *= corr[1];
            }
            #pragma unroll
            for (int nt = 0; nt < 8; nt++) {
                #pragma unroll
                for (int half = 0; half < 2; half++) {
                    float p0 = __expf(sacc[nt][half * 2 + 0] - mrun[half]);
                    float p1 = __expf(sacc[nt][half * 2 + 1] - mrun[half]);
                    psum[half] += p0 + p1;
                    float h0 = to_tf32(p0), h1 = to_tf32(p1);
                    const int row = wrow + g + half * 8;
                    const int col = nt * 8 + t * 2;
                    *(float2*)&sPh[row * APAD + col] = make_float2(h0, h1);
                    *(float2*)&sPl[row * APAD + col] = make_float2(to_tf32(p0 - h0), to_tf32(p1 - h1));
                }
            }
            #pragma unroll
            for (int i = 0; i < 2; i++) {
                psum[i] += __shfl_xor_sync(0xffffffff, psum[i], 1);
                psum[i] += __shfl_xor_sync(0xffffffff, psum[i], 2);
                lrun[i] += psum[i];
            }
            __syncwarp();

            // ---- O += P V ----
            const uint32_t* pPh = (const uint32_t*)sPh;
            const uint32_t* pPl = (const uint32_t*)sPl;
            #pragma unroll
            for (int ks = 0; ks < 8; ks++) {
                uint32_t ah[4], al[4];
                const int abase = (wrow + g) * APAD + ks * 8 + t;
                ah[0] = pPh[abase];                al[0] = pPl[abase];
                ah[1] = pPh[abase + 8 * APAD];     al[1] = pPl[abase + 8 * APAD];
                ah[2] = pPh[abase + 4];            al[2] = pPl[abase + 4];
                ah[3] = pPh[abase + 8 * APAD + 4]; al[3] = pPl[abase + 8 * APAD + 4];
                #pragma unroll
                for (int nt = 0; nt < 8; nt++) {
                    const int bbase = (ks * 8 + t) * APAD + nt * 8 + g;
                    uint32_t bh2[2], bl2[2];
                    bh2[0] = pVh[bbase];  bh2[1] = pVh[bbase + 4 * APAD];
                    bl2[0] = pVl[bbase];  bl2[1] = pVl[bbase + 4 * APAD];
                    mma_tf32(oacc[nt], ah, bh2);
                    mma_tf32(oacc[nt], ah, bl2);
                    mma_tf32(oacc[nt], al, bh2);
                }
            }
            __syncwarp();
        }
        __syncthreads();
    }

    // ---- epilogue: o/l, split, write y hi/lo ----
    const float inv0 = 1.f / lrun[0];
    const float inv1 = 1.f / lrun[1];
    const int r0 = qbase + wrow + g;
    const int r1 = r0 + 8;
    #pragma unroll
    for (int nt = 0; nt < 8; nt++) {
        const int col = h * HD + nt * 8 + t * 2;
        float v0 = oacc[nt][0] * inv0, v1 = oacc[nt][1] * inv0;
        float v2 = oacc[nt][2] * inv1, v3 = oacc[nt][3] * inv1;
        float h0 = to_tf32(v0), h1 = to_tf32(v1), h2 = to_tf32(v2), h3 = to_tf32(v3);
        size_t o0 = (size_t)(b * S_ + r0) * D_ + col;
        size_t o1 = (size_t)(b * S_ + r1) * D_ + col;
        *(float2*)&g_yhi[o0] = make_float2(h0, h1);
        *(float2*)&g_ylo[o0] = make_float2(to_tf32(v0 - h0), to_tf32(v1 - h1));
        *(float2*)&g_yhi[o1] = make_float2(h2, h3);
        *(float2*)&g_ylo[o1] = make_float2(to_tf32(v2 - h2), to_tf32(v3 - h3));
    }
}

// ---------------- launch ----------------
extern "C" void kernel_launch(void* const* d_in, const int* in_sizes, int n_in,
                              void* d_out, int out_size)
{
    const float* x     = (const float*)d_in[0];
    const float* w_qkv = (const float*)d_in[1];
    const float* w_o   = (const float*)d_in[2];
    const int*   amask = (const int*)d_in[3];
    float* out = (float*)d_out;

    float *qkv_p;
    float *xhi, *xlo, *wqh, *wql, *yhi, *ylo, *woh, *wol;
    cudaGetSymbolAddress((void**)&qkv_p, g_qkv);
    cudaGetSymbolAddress((void**)&xhi, g_xhi);
    cudaGetSymbolAddress((void**)&xlo, g_xlo);
    cudaGetSymbolAddress((void**)&wqh, g_wqh);
    cudaGetSymbolAddress((void**)&wql, g_wql);
    cudaGetSymbolAddress((void**)&yhi, g_yhi);
    cudaGetSymbolAddress((void**)&ylo, g_ylo);
    cudaGetSymbolAddress((void**)&woh, g_woh);
    cudaGetSymbolAddress((void**)&wol, g_wol);

    const int smem_gemm = SMEM_GEMM_FLOATS * 4;
    cudaFuncSetAttribute(tf32_gemm_kernel,
                         cudaFuncAttributeMaxDynamicSharedMemorySize, smem_gemm);
    const int smem_attn = SMEM_ATTN_FLOATS * 4;
    cudaFuncSetAttribute(attn_tc_kernel,
                         cudaFuncAttributeMaxDynamicSharedMemorySize, smem_attn);

    rope_table_kernel<<<256, 256>>>();

    split_kernel<<<(B_*S_*D_ + 255) / 256, 256>>>(x, xhi, xlo, B_*S_*D_);
    split_kernel<<<(D_*3*D_ + 255) / 256, 256>>>(w_qkv, wqh, wql, D_*3*D_);
    split_kernel<<<(D_*D_ + 255) / 256, 256>>>(w_o, woh, wol, D_*D_);

    // QKV = x @ w_qkv : [4096,1024] @ [1024,3072]
    tf32_gemm_kernel<<<dim3(3*D_/TBN, B_*S_/TBM), 256, smem_gemm>>>(
        xhi, xlo, wqh, wql, qkv_p, B_*S_, 3*D_, D_);

    rope_split_kernel<<<(B_*S_*D_) / 256, 256>>>();

    attn_tc_kernel<<<dim3(S_/AQ, B_*H_), 256, smem_attn>>>(amask);

    // out = y @ w_o : [4096,1024] @ [1024,1024]
    tf32_gemm_kernel<<<dim3(D_/TBN, B_*S_/TBM), 256, smem_gemm>>>(
        yhi, ylo, woh, wol, out, B_*S_, D_, D_);
}

// round 5
// speedup vs baseline: 2.8705x; 1.7714x over previous
#include <cuda_runtime.h>
#include <cuda_bf16.h>
#include <math.h>
#include <stdint.h>

#define B_  2
#define S_  2048
#define D_  1024
#define H_  16
#define HD  64

// ---------------- scratch (device globals) ----------------
__device__ float g_qkv[B_*S_*3*D_];
__device__ float g_cos[S_*32];
__device__ float g_sin[S_*32];
// bf16 splits, packed pairs-along-K as uint32
__device__ uint32_t g_xhi[B_*S_*D_/2],  g_xlo[B_*S_*D_/2];
__device__ uint32_t g_wqh[3*D_*D_/2],   g_wql[3*D_*D_/2];   // transposed [N][K]
__device__ uint32_t g_woh[D_*D_/2],     g_wol[D_*D_/2];     // transposed [N][K]
__device__ uint32_t g_qhi[B_*H_*S_*HD/2], g_qlo[B_*H_*S_*HD/2];
__device__ uint32_t g_khi[B_*H_*S_*HD/2], g_klo[B_*H_*S_*HD/2];
__device__ uint32_t g_vthi[B_*H_*HD*S_/2], g_vtlo[B_*H_*HD*S_/2]; // V transposed [d][S]
__device__ uint32_t g_yhi[B_*S_*D_/2],  g_ylo[B_*S_*D_/2];

// ---------------- helpers ----------------
__device__ __forceinline__ float bhi(float v) {
    return __bfloat162float(__float2bfloat16(v));
}
// pack two floats to bf16x2: low half = f_low, high half = f_high
__device__ __forceinline__ uint32_t packb(float f_low, float f_high) {
    uint32_t r;
    asm("cvt.rn.bf16x2.f32 %0, %1, %2;" : "=r"(r) : "f"(f_high), "f"(f_low));
    return r;
}
__device__ __forceinline__ void cp16(void* dst, const void* src) {
    uint32_t d = (uint32_t)__cvta_generic_to_shared(dst);
    asm volatile("cp.async.cg.shared.global [%0], [%1], 16;\n" :: "r"(d), "l"(src));
}
__device__ __forceinline__ void cp_commit() {
    asm volatile("cp.async.commit_group;\n");
}
template<int N> __device__ __forceinline__ void cp_wait() {
    asm volatile("cp.async.wait_group %0;\n" :: "n"(N));
}
__device__ __forceinline__ void mma_bf16(float* d, const uint32_t* a, const uint32_t* b) {
    asm volatile(
        "mma.sync.aligned.m16n8k16.row.col.f32.bf16.bf16.f32 "
        "{%0,%1,%2,%3}, {%4,%5,%6,%7}, {%8,%9}, {%0,%1,%2,%3};\n"
        : "+f"(d[0]), "+f"(d[1]), "+f"(d[2]), "+f"(d[3])
        : "r"(a[0]), "r"(a[1]), "r"(a[2]), "r"(a[3]), "r"(b[0]), "r"(b[1]));
}

// ---------------- RoPE table ----------------
__global__ void rope_table_kernel() {
    int idx = blockIdx.x * 256 + threadIdx.x;
    if (idx >= S_ * 32) return;
    int s = idx >> 5;
    int j = idx & 31;
    double inv = pow(10000.0, -((double)(2 * j)) / 64.0);
    double ang = (double)s * inv;
    g_cos[idx] = (float)cos(ang);
    g_sin[idx] = (float)sin(ang);
}

// ---------------- elementwise bf16 split (packed pairs) ----------------
__global__ __launch_bounds__(256) void split2_kernel(
    const float* __restrict__ src, uint32_t* __restrict__ hi, uint32_t* __restrict__ lo, int n2)
{
    int i = blockIdx.x * 256 + threadIdx.x;
    if (i >= n2) return;
    float2 v = ((const float2*)src)[i];
    float h0 = bhi(v.x), h1 = bhi(v.y);
    hi[i] = packb(h0, h1);
    lo[i] = packb(v.x - h0, v.y - h1);
}

// ---------------- weight transpose + bf16 split: w[K][N] -> wt[N][K] ----------------
__global__ __launch_bounds__(256) void wsplit_t_kernel(
    const float* __restrict__ w, uint32_t* __restrict__ th, uint32_t* __restrict__ tl,
    int Kd, int Nd)
{
    __shared__ float tile[32][33];
    int n0 = blockIdx.x * 32, k0 = blockIdx.y * 32;
    int tx = threadIdx.x & 31, ty = threadIdx.x >> 5;   // ty 0..7
    #pragma unroll
    for (int r = 0; r < 32; r += 8)
        tile[ty + r][tx] = w[(size_t)(k0 + ty + r) * Nd + n0 + tx];
    __syncthreads();
    __nv_bfloat16* thb = (__nv_bfloat16*)th;
    __nv_bfloat16* tlb = (__nv_bfloat16*)tl;
    #pragma unroll
    for (int r = 0; r < 32; r += 8) {
        int n = n0 + ty + r, k = k0 + tx;
        float v = tile[tx][ty + r];
        float h = bhi(v);
        thb[(size_t)n * Kd + k] = __float2bfloat16(h);
        tlb[(size_t)n * Kd + k] = __float2bfloat16(v - h);
    }
}

// ---------------- RoPE + transpose + bf16 split (V transposed to [d][S]) ----------------
__global__ __launch_bounds__(256) void rope_split_kernel() {
    __shared__ float vt[64][33];
    const int blk = blockIdx.x;              // B*H*(S/32) = 2048 blocks
    const int bh = blk >> 6;
    const int stile = (blk & 63) * 32;
    const int b = bh >> 4, h = bh & 15;
    const int tid = threadIdx.x;
    const int i = tid & 63, sl0 = tid >> 6;  // 0..3

    __nv_bfloat16* qhb = (__nv_bfloat16*)g_qhi;
    __nv_bfloat16* qlb = (__nv_bfloat16*)g_qlo;
    __nv_bfloat16* khb = (__nv_bfloat16*)g_khi;
    __nv_bfloat16* klb = (__nv_bfloat16*)g_klo;

    for (int sl = sl0; sl < 32; sl += 4) {
        int s = stile + sl;
        const float* row = g_qkv + (size_t)(b * S_ + s) * 3 * D_;
        int j = i & 31;
        float c  = g_cos[s * 32 + j];
        float sn = g_sin[s * 32 + j];
        float qv = row[h * 64 + i];
        float qp = row[h * 64 + (i ^ 32)];
        float kv = row[D_ + h * 64 + i];
        float kp = row[D_ + h * 64 + (i ^ 32)];
        float vv = row[2 * D_ + h * 64 + i];
        float sg = (i < 32) ? -1.f : 1.f;
        float qo = (qv * c + sg * qp * sn) * 0.125f;   // fold 1/sqrt(64)
        float ko = kv * c + sg * kp * sn;
        size_t o = ((size_t)bh * S_ + s) * HD + i;
        float qh = bhi(qo); qhb[o] = __float2bfloat16(qh); qlb[o] = __float2bfloat16(qo - qh);
        float kh = bhi(ko); khb[o] = __float2bfloat16(kh); klb[o] = __float2bfloat16(ko - kh);
        vt[i][sl] = vv;
    }
    __syncthreads();
    const int d = tid >> 2, p = tid & 3;
    uint32_t oh[4], ol[4];
    #pragma unroll
    for (int e = 0; e < 4; e++) {
        int s0 = p * 8 + e * 2;
        float v0 = vt[d][s0], v1 = vt[d][s0 + 1];
        float h0 = bhi(v0), h1 = bhi(v1);
        oh[e] = packb(h0, h1);
        ol[e] = packb(v0 - h0, v1 - h1);
    }
    size_t vo = (size_t)bh * HD * (S_/2) + (size_t)d * (S_/2) + (stile >> 1) + p * 4;
    *(uint4*)&g_vthi[vo] = *(uint4*)oh;
    *(uint4*)&g_vtlo[vo] = *(uint4*)ol;
}

// ---------------- 3-product bf16 GEMM: C[M,N] = A[M,K] @ Bt[N,K]^T ----------------
// A, Bt bf16 hi/lo packed pairs along K (uint32 [rows][K/2]). 2-stage cp.async.
#define KS 20            // smem row stride (uint32) for 16-pair rows
#define G_AH 0
#define G_AL 2560
#define G_BH 5120
#define G_BL 7680
#define G_STAGE 10240
#define SMEM_GEMM_U32 (2*G_STAGE)

__device__ __forceinline__ void gemm_stage_load(
    uint32_t* st, const uint32_t* Ah, const uint32_t* Al,
    const uint32_t* Bh, const uint32_t* Bl, int kp0, int tid, int Kp)
{
    const int row = tid >> 1;          // 0..127
    const int c = (tid & 1) * 8;       // 0 or 8
    const size_t ga = (size_t)row * Kp + kp0 + c;
    cp16(&st[G_AH + row * KS + c],     Ah + ga);
    cp16(&st[G_AH + row * KS + c + 4], Ah + ga + 4);
    cp16(&st[G_AL + row * KS + c],     Al + ga);
    cp16(&st[G_AL + row * KS + c + 4], Al + ga + 4);
    cp16(&st[G_BH + row * KS + c],     Bh + ga);
    cp16(&st[G_BH + row * KS + c + 4], Bh + ga + 4);
    cp16(&st[G_BL + row * KS + c],     Bl + ga);
    cp16(&st[G_BL + row * KS + c + 4], Bl + ga + 4);
}

__global__ __launch_bounds__(256, 2) void bf16_gemm_kernel(
    const uint32_t* __restrict__ Ahi, const uint32_t* __restrict__ Alo,
    const uint32_t* __restrict__ Bhi, const uint32_t* __restrict__ Blo,
    float* __restrict__ C, int M, int N, int K)
{
    extern __shared__ uint32_t smg[];
    const int Kp = K >> 1;
    const int tid  = threadIdx.x;
    const int warp = tid >> 5;
    const int lane = tid & 31;
    const int g = lane >> 2;
    const int t = lane & 3;
    const int mBase = (warp >> 1) * 32;
    const int nBase = (warp & 1) * 64;

    Ahi += (size_t)blockIdx.y * 128 * Kp;
    Alo += (size_t)blockIdx.y * 128 * Kp;
    Bhi += (size_t)blockIdx.x * 128 * Kp;
    Blo += (size_t)blockIdx.x * 128 * Kp;

    float acc[2][8][4];
    #pragma unroll
    for (int mt = 0; mt < 2; mt++)
        #pragma unroll
        for (int nt = 0; nt < 8; nt++)
            #pragma unroll
            for (int r = 0; r < 4; r++) acc[mt][nt][r] = 0.f;

    const int NT = Kp / 16;   // 32 pairs... 16 pairs per tile (K=32 elems)
    gemm_stage_load(smg, Ahi, Alo, Bhi, Blo, 0, tid, Kp);
    cp_commit();

    for (int it = 0; it < NT; it++) {
        if (it + 1 < NT) {
            gemm_stage_load(smg + ((it + 1) & 1) * G_STAGE, Ahi, Alo, Bhi, Blo,
                            (it + 1) * 16, tid, Kp);
            cp_commit();
            cp_wait<1>();
        } else {
            cp_wait<0>();
        }
        __syncthreads();

        const uint32_t* st = smg + (it & 1) * G_STAGE;
        const uint32_t* pAh = st + G_AH;
        const uint32_t* pAl = st + G_AL;
        const uint32_t* pBh = st + G_BH;
        const uint32_t* pBl = st + G_BL;

        #pragma unroll
        for (int kstep = 0; kstep < 2; kstep++) {
            const int k8 = kstep * 8;
            uint32_t ah[2][4], al[2][4];
            #pragma unroll
            for (int mt = 0; mt < 2; mt++) {
                const int base = (mBase + mt * 16 + g) * KS + k8 + t;
                ah[mt][0] = pAh[base];       ah[mt][1] = pAh[base + 160];
                ah[mt][2] = pAh[base + 4];   ah[mt][3] = pAh[base + 164];
                al[mt][0] = pAl[base];       al[mt][1] = pAl[base + 160];
                al[mt][2] = pAl[base + 4];   al[mt][3] = pAl[base + 164];
            }
            #pragma unroll
            for (int nt = 0; nt < 8; nt++) {
                const int bb = (nBase + nt * 8 + g) * KS + k8 + t;
                uint32_t bh2[2] = {pBh[bb], pBh[bb + 4]};
                uint32_t bl2[2] = {pBl[bb], pBl[bb + 4]};
                #pragma unroll
                for (int mt = 0; mt < 2; mt++) {
                    mma_bf16(acc[mt][nt], ah[mt], bh2);
                    mma_bf16(acc[mt][nt], ah[mt], bl2);
                    mma_bf16(acc[mt][nt], al[mt], bh2);
                }
            }
        }
        __syncthreads();
    }

    C += (size_t)blockIdx.y * 128 * N + blockIdx.x * 128;
    #pragma unroll
    for (int mt = 0; mt < 2; mt++) {
        const int r0 = mBase + mt * 16 + g;
        #pragma unroll
        for (int nt = 0; nt < 8; nt++) {
            const int c = nBase + nt * 8 + t * 2;
            *(float2*)&C[(size_t)r0 * N + c]       = make_float2(acc[mt][nt][0], acc[mt][nt][1]);
            *(float2*)&C[(size_t)(r0 + 8) * N + c] = make_float2(acc[mt][nt][2], acc[mt][nt][3]);
        }
    }
}

// ---------------- bf16 tensor-core causal flash attention ----------------
#define APS 36
#define A_PH 0
#define A_PL 4608
#define A_KV 9216
#define KV_KH 0
#define KV_KL 2304
#define KV_VH 4608
#define KV_VL 6912
#define KV_STAGE 9216
#define A_MSK (A_KV + 2*KV_STAGE)
#define SMEM_ATTN_U32 (A_MSK + S_)

__device__ __forceinline__ void attn_stage_load(
    uint32_t* sma, int st,
    const uint32_t* kh, const uint32_t* kl,
    const uint32_t* vh, const uint32_t* vl, int kt, int tid)
{
    uint32_t* base = sma + A_KV + st * KV_STAGE;
    const int r = tid >> 2, c = tid & 3;
    const size_t gk = (size_t)(kt * 64 + r) * 32;
    cp16(&base[KV_KH + r * APS + c * 4],       kh + gk + c * 4);
    cp16(&base[KV_KH + r * APS + (c + 4) * 4], kh + gk + (c + 4) * 4);
    cp16(&base[KV_KL + r * APS + c * 4],       kl + gk + c * 4);
    cp16(&base[KV_KL + r * APS + (c + 4) * 4], kl + gk + (c + 4) * 4);
    const size_t gv = (size_t)r * (S_/2) + kt * 32;
    cp16(&base[KV_VH + r * APS + c * 4],       vh + gv + c * 4);
    cp16(&base[KV_VH + r * APS + (c + 4) * 4], vh + gv + (c + 4) * 4);
    cp16(&base[KV_VL + r * APS + c * 4],       vl + gv + c * 4);
    cp16(&base[KV_VL + r * APS + (c + 4) * 4], vl + gv + (c + 4) * 4);
}

__global__ __launch_bounds__(256, 1) void attn_tc_kernel(const int* __restrict__ amask) {
    extern __shared__ uint32_t sma[];
    uint32_t* sPh = sma + A_PH;
    uint32_t* sPl = sma + A_PL;
    float* sMf = (float*)(sma + A_MSK);

    const int tid  = threadIdx.x;
    const int warp = tid >> 5;
    const int lane = tid & 31;
    const int g = lane >> 2;
    const int t = lane & 3;
    const int bh = blockIdx.y;
    const int b  = bh >> 4;
    const int h  = bh & 15;
    const int qbase = blockIdx.x * 128;
    const int wrow  = warp * 16;

    const uint32_t* kh = g_khi + (size_t)bh * S_ * 32;
    const uint32_t* kl = g_klo + (size_t)bh * S_ * 32;
    const uint32_t* vh = g_vthi + (size_t)bh * HD * (S_/2);
    const uint32_t* vl = g_vtlo + (size_t)bh * HD * (S_/2);

    const int nkt = (qbase + 128) / 64;

    attn_stage_load(sma, 0, kh, kl, vh, vl, 0, tid);
    cp_commit();

    // stage Q through sP, also mask row
    {
        const uint32_t* qgh = g_qhi + ((size_t)bh * S_ + qbase) * 32;
        const uint32_t* qgl = g_qlo + ((size_t)bh * S_ + qbase) * 32;
        for (int idx = tid; idx < 1024; idx += 256) {
            int r = idx >> 3, c4 = (idx & 7) * 4;
            *(uint4*)&sPh[r * APS + c4] = *(const uint4*)(qgh + r * 32 + c4);
            *(uint4*)&sPl[r * APS + c4] = *(const uint4*)(qgl + r * 32 + c4);
        }
        for (int idx = tid; idx < S_; idx += 256)
            sMf[idx] = (amask[b * S_ + idx] == 0) ? -INFINITY : 0.f;
    }
    __syncthreads();

    uint32_t Qh[4][4], Ql[4][4];
    #pragma unroll
    for (int ks = 0; ks < 4; ks++) {
        const int base = (wrow + g) * APS + ks * 8 + t;
        Qh[ks][0] = sPh[base];           Ql[ks][0] = sPl[base];
        Qh[ks][1] = sPh[base + 8*APS];   Ql[ks][1] = sPl[base + 8*APS];
        Qh[ks][2] = sPh[base + 4];       Ql[ks][2] = sPl[base + 4];
        Qh[ks][3] = sPh[base + 8*APS+4]; Ql[ks][3] = sPl[base + 8*APS+4];
    }
    // each warp reads/writes only its own 16 sP rows from here on

    float oacc[8][4];
    #pragma unroll
    for (int nt = 0; nt < 8; nt++)
        #pragma unroll
        for (int r = 0; r < 4; r++) oacc[nt][r] = 0.f;
    float mrun[2] = {-INFINITY, -INFINITY};
    float lrun[2] = {0.f, 0.f};

    for (int kt = 0; kt < nkt; kt++) {
        if (kt + 1 < nkt) {
            attn_stage_load(sma, (kt + 1) & 1, kh, kl, vh, vl, kt + 1, tid);
            cp_commit();
            cp_wait<1>();
        } else {
            cp_wait<0>();
        }
        __syncthreads();

        if (kt * 64 <= qbase + wrow + 15) {
            uint32_t* stg = sma + A_KV + (kt & 1) * KV_STAGE;
            const uint32_t* pKh = stg + KV_KH;
            const uint32_t* pKl = stg + KV_KL;
            const uint32_t* pVh = stg + KV_VH;
            const uint32_t* pVl = stg + KV_VL;

            // ---- S = Q K^T ----
            float sacc[8][4];
            #pragma unroll
            for (int nt = 0; nt < 8; nt++)
                #pragma unroll
                for (int r = 0; r < 4; r++) sacc[nt][r] = 0.f;

            #pragma unroll
            for (int ks = 0; ks < 4; ks++) {
                #pragma unroll
                for (int nt = 0; nt < 8; nt++) {
                    const int bb = (nt * 8 + g) * APS + ks * 8 + t;
                    uint32_t bh2[2] = {pKh[bb], pKh[bb + 4]};
                    uint32_t bl2[2] = {pKl[bb], pKl[bb + 4]};
                    mma_bf16(sacc[nt], Qh[ks], bh2);
                    mma_bf16(sacc[nt], Qh[ks], bl2);
                    mma_bf16(sacc[nt], Ql[ks], bh2);
                }
            }

            // ---- masks + row max ----
            const bool diag = (kt * 64 + 63) > (qbase + wrow);
            float tmax[2] = {-INFINITY, -INFINITY};
            #pragma unroll
            for (int nt = 0; nt < 8; nt++) {
                #pragma unroll
                for (int e = 0; e < 4; e++) {
                    const int colL = nt * 8 + t * 2 + (e & 1);
                    float v = sacc[nt][e] + sMf[kt * 64 + colL];
                    if (diag) {
                        const int row = qbase + wrow + g + ((e >> 1) << 3);
                        const int col = kt * 64 + colL;
                        if (col > row) v = -INFINITY;
                    }
                    sacc[nt][e] = v;
                    tmax[e >> 1] = fmaxf(tmax[e >> 1], v);
                }
            }
            #pragma unroll
            for (int i = 0; i < 2; i++) {
                tmax[i] = fmaxf(tmax[i], __shfl_xor_sync(0xffffffff, tmax[i], 1));
                tmax[i] = fmaxf(tmax[i], __shfl_xor_sync(0xffffffff, tmax[i], 2));
            }

            // ---- online softmax ----
            float corr[2], psum[2] = {0.f, 0.f};
            #pragma unroll
            for (int i = 0; i < 2; i++) {
                float mnew = fmaxf(mrun[i], tmax[i]);
                corr[i] = __expf(mrun[i] - mnew);
                mrun[i] = mnew;
                lrun[i] *= corr[i];
            }
            #pragma unroll
            for (int nt = 0; nt < 8; nt++) {
                oacc[nt][0] *= corr[0]; oacc[nt][1] *= corr[0];
                oacc[nt][2] *= corr[1]; oacc[nt][3] *= corr[1];
            }
            #pragma unroll
            for (int nt = 0; nt < 8; nt++) {
                #pragma unroll
                for (int half = 0; half < 2; half++) {
                    float p0 = __expf(sacc[nt][half * 2 + 0] - mrun[half]);
                    float p1 = __expf(sacc[nt][half * 2 + 1] - mrun[half]);
                    psum[half] += p0 + p1;
                    float h0 = bhi(p0), h1 = bhi(p1);
                    const int row = wrow + g + half * 8;
                    sPh[row * APS + nt * 4 + t] = packb(h0, h1);
                    sPl[row * APS + nt * 4 + t] = packb(p0 - h0, p1 - h1);
                }
            }
            #pragma unroll
            for (int i = 0; i < 2; i++) {
                psum[i] += __shfl_xor_sync(0xffffffff, psum[i], 1);
                psum[i] += __shfl_xor_sync(0xffffffff, psum[i], 2);
                lrun[i] += psum[i];
            }
            __syncwarp();

            // ---- O += P V ----
            #pragma unroll
            for (int ks = 0; ks < 4; ks++) {
                uint32_t ah[4], al[4];
                const int abase = (wrow + g) * APS + ks * 8 + t;
                ah[0] = sPh[abase];             al[0] = sPl[abase];
                ah[1] = sPh[abase + 8*APS];     al[1] = sPl[abase + 8*APS];
                ah[2] = sPh[abase + 4];         al[2] = sPl[abase + 4];
                ah[3] = sPh[abase + 8*APS + 4]; al[3] = sPl[abase + 8*APS + 4];
                #pragma unroll
                for (int nt = 0; nt < 8; nt++) {
                    const int bb = (nt * 8 + g) * APS + ks * 8 + t;
                    uint32_t bh2[2] = {pVh[bb], pVh[bb + 4]};
                    uint32_t bl2[2] = {pVl[bb], pVl[bb + 4]};
                    mma_bf16(oacc[nt], ah, bh2);
                    mma_bf16(oacc[nt], ah, bl2);
                    mma_bf16(oacc[nt], al, bh2);
                }
            }
            __syncwarp();
        }
        __syncthreads();
    }

    // ---- epilogue: o/l, bf16 split, packed write ----
    const float inv0 = 1.f / lrun[0];
    const float inv1 = 1.f / lrun[1];
    const int r0 = qbase + wrow + g;
    const int r1 = r0 + 8;
    #pragma unroll
    for (int nt = 0; nt < 8; nt++) {
        float v0 = oacc[nt][0] * inv0, v1 = oacc[nt][1] * inv0;
        float v2 = oacc[nt][2] * inv1, v3 = oacc[nt][3] * inv1;
        const size_t o0 = (size_t)(b * S_ + r0) * 512 + h * 32 + nt * 4 + t;
        const size_t o1 = (size_t)(b * S_ + r1) * 512 + h * 32 + nt * 4 + t;
        float h0 = bhi(v0), h1 = bhi(v1), h2 = bhi(v2), h3 = bhi(v3);
        g_yhi[o0] = packb(h0, h1);
        g_ylo[o0] = packb(v0 - h0, v1 - h1);
        g_yhi[o1] = packb(h2, h3);
        g_ylo[o1] = packb(v2 - h2, v3 - h3);
    }
}

// ---------------- launch ----------------
extern "C" void kernel_launch(void* const* d_in, const int* in_sizes, int n_in,
                              void* d_out, int out_size)
{
    const float* x     = (const float*)d_in[0];
    const float* w_qkv = (const float*)d_in[1];
    const float* w_o   = (const float*)d_in[2];
    const int*   amask = (const int*)d_in[3];
    float* out = (float*)d_out;

    float* qkv_p;
    uint32_t *xhi, *xlo, *wqh, *wql, *woh, *wol, *yhi, *ylo;
    cudaGetSymbolAddress((void**)&qkv_p, g_qkv);
    cudaGetSymbolAddress((void**)&xhi, g_xhi);
    cudaGetSymbolAddress((void**)&xlo, g_xlo);
    cudaGetSymbolAddress((void**)&wqh, g_wqh);
    cudaGetSymbolAddress((void**)&wql, g_wql);
    cudaGetSymbolAddress((void**)&woh, g_woh);
    cudaGetSymbolAddress((void**)&wol, g_wol);
    cudaGetSymbolAddress((void**)&yhi, g_yhi);
    cudaGetSymbolAddress((void**)&ylo, g_ylo);

    const int smem_gemm = SMEM_GEMM_U32 * 4;
    cudaFuncSetAttribute(bf16_gemm_kernel,
                         cudaFuncAttributeMaxDynamicSharedMemorySize, smem_gemm);
    const int smem_attn = SMEM_ATTN_U32 * 4;
    cudaFuncSetAttribute(attn_tc_kernel,
                         cudaFuncAttributeMaxDynamicSharedMemorySize, smem_attn);

    rope_table_kernel<<<256, 256>>>();

    split2_kernel<<<(B_*S_*D_/2 + 255) / 256, 256>>>(x, xhi, xlo, B_*S_*D_/2);
    wsplit_t_kernel<<<dim3(3*D_/32, D_/32), 256>>>(w_qkv, wqh, wql, D_, 3*D_);
    wsplit_t_kernel<<<dim3(D_/32, D_/32), 256>>>(w_o, woh, wol, D_, D_);

    // QKV = x @ w_qkv
    bf16_gemm_kernel<<<dim3(3*D_/128, B_*S_/128), 256, smem_gemm>>>(
        xhi, xlo, wqh, wql, qkv_p, B_*S_, 3*D_, D_);

    rope_split_kernel<<<B_*H_*(S_/32), 256>>>();

    attn_tc_kernel<<<dim3(S_/128, B_*H_), 256, smem_attn>>>(amask);

    // out = y @ w_o
    bf16_gemm_kernel<<<dim3(D_/128, B_*S_/128), 256, smem_gemm>>>(
        yhi, ylo, woh, wol, out, B_*S_, D_, D_);
}

// round 7
// speedup vs baseline: 4.3361x; 1.5106x over previous
#include <cuda_runtime.h>
#include <cuda_fp16.h>
#include <math.h>
#include <stdint.h>

#define B_  2
#define S_  2048
#define D_  1024
#define H_  16
#define HD  64

// ---------------- scratch (device globals) ----------------
__device__ float g_qkv[B_*S_*3*D_];
__device__ float g_cos[S_*32];
__device__ float g_sin[S_*32];
// fp16 packed pairs-along-K as uint32. A-side: hi+lo. B-side: hi only.
__device__ uint32_t g_xhi[B_*S_*D_/2],  g_xlo[B_*S_*D_/2];
__device__ uint32_t g_wqh[3*D_*D_/2];                       // transposed [N][K]
__device__ uint32_t g_woh[D_*D_/2];                         // transposed [N][K]
__device__ uint32_t g_qhi[B_*H_*S_*HD/2], g_qlo[B_*H_*S_*HD/2];
__device__ uint32_t g_khi[B_*H_*S_*HD/2];
__device__ uint32_t g_vthi[B_*H_*HD*S_/2];                  // V transposed [d][S]
__device__ uint32_t g_yhi[B_*S_*D_/2],  g_ylo[B_*S_*D_/2];

// ---------------- helpers ----------------
__device__ __forceinline__ float hhi(float v) {
    return __half2float(__float2half_rn(v));
}
// pack two floats to fp16x2: low half = f_low, high half = f_high
__device__ __forceinline__ uint32_t packh(float f_low, float f_high) {
    uint32_t r;
    asm("cvt.rn.f16x2.f32 %0, %1, %2;" : "=r"(r) : "f"(f_high), "f"(f_low));
    return r;
}
__device__ __forceinline__ void cp16(void* dst, const void* src) {
    uint32_t d = (uint32_t)__cvta_generic_to_shared(dst);
    asm volatile("cp.async.cg.shared.global [%0], [%1], 16;\n" :: "r"(d), "l"(src));
}
__device__ __forceinline__ void cp_commit() {
    asm volatile("cp.async.commit_group;\n");
}
template<int N> __device__ __forceinline__ void cp_wait() {
    asm volatile("cp.async.wait_group %0;\n" :: "n"(N));
}
__device__ __forceinline__ void mma_f16(float* d, const uint32_t* a, const uint32_t* b) {
    asm volatile(
        "mma.sync.aligned.m16n8k16.row.col.f32.f16.f16.f32 "
        "{%0,%1,%2,%3}, {%4,%5,%6,%7}, {%8,%9}, {%0,%1,%2,%3};\n"
        : "+f"(d[0]), "+f"(d[1]), "+f"(d[2]), "+f"(d[3])
        : "r"(a[0]), "r"(a[1]), "r"(a[2]), "r"(a[3]), "r"(b[0]), "r"(b[1]));
}

// ---------------- RoPE table ----------------
__global__ void rope_table_kernel() {
    int idx = blockIdx.x * 256 + threadIdx.x;
    if (idx >= S_ * 32) return;
    int s = idx >> 5;
    int j = idx & 31;
    double inv = pow(10000.0, -((double)(2 * j)) / 64.0);
    double ang = (double)s * inv;
    g_cos[idx] = (float)cos(ang);
    g_sin[idx] = (float)sin(ang);
}

// ---------------- elementwise fp16 hi/lo split (packed pairs) ----------------
__global__ __launch_bounds__(256) void split2_kernel(
    const float* __restrict__ src, uint32_t* __restrict__ hi, uint32_t* __restrict__ lo, int n2)
{
    int i = blockIdx.x * 256 + threadIdx.x;
    if (i >= n2) return;
    float2 v = ((const float2*)src)[i];
    float h0 = hhi(v.x), h1 = hhi(v.y);
    hi[i] = packh(h0, h1);
    lo[i] = packh(v.x - h0, v.y - h1);
}

// ---------------- weight transpose + fp16 quantize: w[K][N] -> wt[N][K] (hi only) ----------------
__global__ __launch_bounds__(256) void wsplit_t_kernel(
    const float* __restrict__ w, uint32_t* __restrict__ th, int Kd, int Nd)
{
    __shared__ float tile[32][33];
    int n0 = blockIdx.x * 32, k0 = blockIdx.y * 32;
    int tx = threadIdx.x & 31, ty = threadIdx.x >> 5;
    #pragma unroll
    for (int r = 0; r < 32; r += 8)
        tile[ty + r][tx] = w[(size_t)(k0 + ty + r) * Nd + n0 + tx];
    __syncthreads();
    __half* thb = (__half*)th;
    #pragma unroll
    for (int r = 0; r < 32; r += 8) {
        int n = n0 + ty + r, k = k0 + tx;
        thb[(size_t)n * Kd + k] = __float2half_rn(tile[tx][ty + r]);
    }
}

// ---------------- RoPE + transpose + fp16 split (Q hi/lo; K hi; V hi transposed [d][S]) ----------------
__global__ __launch_bounds__(256) void rope_split_kernel() {
    __shared__ float vt[64][33];
    const int blk = blockIdx.x;
    const int bh = blk >> 6;
    const int stile = (blk & 63) * 32;
    const int b = bh >> 4, h = bh & 15;
    const int tid = threadIdx.x;
    const int i = tid & 63, sl0 = tid >> 6;

    __half* qhb = (__half*)g_qhi;
    __half* qlb = (__half*)g_qlo;
    __half* khb = (__half*)g_khi;

    for (int sl = sl0; sl < 32; sl += 4) {
        int s = stile + sl;
        const float* row = g_qkv + (size_t)(b * S_ + s) * 3 * D_;
        int j = i & 31;
        float c  = g_cos[s * 32 + j];
        float sn = g_sin[s * 32 + j];
        float qv = row[h * 64 + i];
        float qp = row[h * 64 + (i ^ 32)];
        float kv = row[D_ + h * 64 + i];
        float kp = row[D_ + h * 64 + (i ^ 32)];
        float vv = row[2 * D_ + h * 64 + i];
        float sg = (i < 32) ? -1.f : 1.f;
        float qo = (qv * c + sg * qp * sn) * 0.125f;   // fold 1/sqrt(64)
        float ko = kv * c + sg * kp * sn;
        size_t o = ((size_t)bh * S_ + s) * HD + i;
        float qh = hhi(qo);
        qhb[o] = __float2half_rn(qh);
        qlb[o] = __float2half_rn(qo - qh);
        khb[o] = __float2half_rn(ko);
        vt[i][sl] = vv;
    }
    __syncthreads();
    const int d = tid >> 2, p = tid & 3;
    uint32_t oh[4];
    #pragma unroll
    for (int e = 0; e < 4; e++) {
        int s0 = p * 8 + e * 2;
        oh[e] = packh(vt[d][s0], vt[d][s0 + 1]);
    }
    size_t vo = (size_t)bh * HD * (S_/2) + (size_t)d * (S_/2) + (stile >> 1) + p * 4;
    *(uint4*)&g_vthi[vo] = *(uint4*)oh;
}

// ---------------- fp16 2-product GEMM: C[M,N] = A[M,K] @ Bt[N,K]^T ----------------
// A hi/lo + B hi, packed pairs along K (uint32 [rows][K/2]). 2-stage cp.async.
#define KS 20            // smem row stride (uint32) for 16-pair rows
#define G_AH 0
#define G_AL 2560
#define G_BH 5120
#define G_STAGE 7680
#define SMEM_GEMM_U32 (2*G_STAGE)

__device__ __forceinline__ void gemm_stage_load(
    uint32_t* st, const uint32_t* Ah, const uint32_t* Al, const uint32_t* Bh,
    int kp0, int tid, int Kp)
{
    const int row = tid >> 1;          // 0..127
    const int c = (tid & 1) * 8;       // 0 or 8
    const size_t ga = (size_t)row * Kp + kp0 + c;
    cp16(&st[G_AH + row * KS + c],     Ah + ga);
    cp16(&st[G_AH + row * KS + c + 4], Ah + ga + 4);
    cp16(&st[G_AL + row * KS + c],     Al + ga);
    cp16(&st[G_AL + row * KS + c + 4], Al + ga + 4);
    cp16(&st[G_BH + row * KS + c],     Bh + ga);
    cp16(&st[G_BH + row * KS + c + 4], Bh + ga + 4);
}

__global__ __launch_bounds__(256, 2) void f16_gemm_kernel(
    const uint32_t* __restrict__ Ahi, const uint32_t* __restrict__ Alo,
    const uint32_t* __restrict__ Bhi,
    float* __restrict__ C, int M, int N, int K)
{
    extern __shared__ uint32_t smg[];
    const int Kp = K >> 1;
    const int tid  = threadIdx.x;
    const int warp = tid >> 5;
    const int lane = tid & 31;
    const int g = lane >> 2;
    const int t = lane & 3;
    const int mBase = (warp >> 1) * 32;
    const int nBase = (warp & 1) * 64;

    Ahi += (size_t)blockIdx.y * 128 * Kp;
    Alo += (size_t)blockIdx.y * 128 * Kp;
    Bhi += (size_t)blockIdx.x * 128 * Kp;

    float acc[2][8][4];
    #pragma unroll
    for (int mt = 0; mt < 2; mt++)
        #pragma unroll
        for (int nt = 0; nt < 8; nt++)
            #pragma unroll
            for (int r = 0; r < 4; r++) acc[mt][nt][r] = 0.f;

    const int NT = Kp / 16;
    gemm_stage_load(smg, Ahi, Alo, Bhi, 0, tid, Kp);
    cp_commit();

    for (int it = 0; it < NT; it++) {
        if (it + 1 < NT) {
            gemm_stage_load(smg + ((it + 1) & 1) * G_STAGE, Ahi, Alo, Bhi,
                            (it + 1) * 16, tid, Kp);
            cp_commit();
            cp_wait<1>();
        } else {
            cp_wait<0>();
        }
        __syncthreads();

        const uint32_t* st = smg + (it & 1) * G_STAGE;
        const uint32_t* pAh = st + G_AH;
        const uint32_t* pAl = st + G_AL;
        const uint32_t* pBh = st + G_BH;

        #pragma unroll
        for (int kstep = 0; kstep < 2; kstep++) {
            const int k8 = kstep * 8;
            uint32_t ah[2][4], al[2][4];
            #pragma unroll
            for (int mt = 0; mt < 2; mt++) {
                const int base = (mBase + mt * 16 + g) * KS + k8 + t;
                ah[mt][0] = pAh[base];       ah[mt][1] = pAh[base + 160];
                ah[mt][2] = pAh[base + 4];   ah[mt][3] = pAh[base + 164];
                al[mt][0] = pAl[base];       al[mt][1] = pAl[base + 160];
                al[mt][2] = pAl[base + 4];   al[mt][3] = pAl[base + 164];
            }
            #pragma unroll
            for (int nt = 0; nt < 8; nt++) {
                const int bb = (nBase + nt * 8 + g) * KS + k8 + t;
                uint32_t bh2[2] = {pBh[bb], pBh[bb + 4]};
                #pragma unroll
                for (int mt = 0; mt < 2; mt++) {
                    mma_f16(acc[mt][nt], ah[mt], bh2);
                    mma_f16(acc[mt][nt], al[mt], bh2);
                }
            }
        }
        __syncthreads();
    }

    C += (size_t)blockIdx.y * 128 * N + blockIdx.x * 128;
    #pragma unroll
    for (int mt = 0; mt < 2; mt++) {
        const int r0 = mBase + mt * 16 + g;
        #pragma unroll
        for (int nt = 0; nt < 8; nt++) {
            const int c = nBase + nt * 8 + t * 2;
            *(float2*)&C[(size_t)r0 * N + c]       = make_float2(acc[mt][nt][0], acc[mt][nt][1]);
            *(float2*)&C[(size_t)(r0 + 8) * N + c] = make_float2(acc[mt][nt][2], acc[mt][nt][3]);
        }
    }
}

// ---------------- fp16 tensor-core causal flash attention ----------------
#define APS 36
#define A_PH 0
#define A_PL 4608
#define A_KV 9216
#define KV_KH 0
#define KV_VH 2304
#define KV_STAGE 4608
#define A_MSK (A_KV + 2*KV_STAGE)
#define SMEM_ATTN_U32 (A_MSK + S_)

__device__ __forceinline__ void attn_stage_load(
    uint32_t* sma, int st, const uint32_t* kh, const uint32_t* vh, int kt, int tid)
{
    uint32_t* base = sma + A_KV + st * KV_STAGE;
    const int r = tid >> 2, c = tid & 3;
    const size_t gk = (size_t)(kt * 64 + r) * 32;
    cp16(&base[KV_KH + r * APS + c * 4],       kh + gk + c * 4);
    cp16(&base[KV_KH + r * APS + (c + 4) * 4], kh + gk + (c + 4) * 4);
    const size_t gv = (size_t)r * (S_/2) + kt * 32;
    cp16(&base[KV_VH + r * APS + c * 4],       vh + gv + c * 4);
    cp16(&base[KV_VH + r * APS + (c + 4) * 4], vh + gv + (c + 4) * 4);
}

__global__ __launch_bounds__(256, 1) void attn_tc_kernel(const int* __restrict__ amask) {
    extern __shared__ uint32_t sma[];
    uint32_t* sPh = sma + A_PH;
    uint32_t* sPl = sma + A_PL;
    float* sMf = (float*)(sma + A_MSK);

    const int tid  = threadIdx.x;
    const int warp = tid >> 5;
    const int lane = tid & 31;
    const int g = lane >> 2;
    const int t = lane & 3;
    // LPT ordering: heaviest q-tiles first
    const int qtile = (S_ / 128 - 1) - (int)(blockIdx.x >> 5);
    const int bh    = blockIdx.x & 31;
    const int b  = bh >> 4;
    const int h  = bh & 15;
    const int qbase = qtile * 128;
    const int wrow  = warp * 16;

    const uint32_t* kh = g_khi + (size_t)bh * S_ * 32;
    const uint32_t* vh = g_vthi + (size_t)bh * HD * (S_/2);

    const int nkt = (qbase + 128) / 64;

    attn_stage_load(sma, 0, kh, vh, 0, tid);
    cp_commit();

    {
        const uint32_t* qgh = g_qhi + ((size_t)bh * S_ + qbase) * 32;
        const uint32_t* qgl = g_qlo + ((size_t)bh * S_ + qbase) * 32;
        for (int idx = tid; idx < 1024; idx += 256) {
            int r = idx >> 3, c4 = (idx & 7) * 4;
            *(uint4*)&sPh[r * APS + c4] = *(const uint4*)(qgh + r * 32 + c4);
            *(uint4*)&sPl[r * APS + c4] = *(const uint4*)(qgl + r * 32 + c4);
        }
        for (int idx = tid; idx < S_; idx += 256)
            sMf[idx] = (amask[b * S_ + idx] == 0) ? -INFINITY : 0.f;
    }
    __syncthreads();

    uint32_t Qh[4][4], Ql[4][4];
    #pragma unroll
    for (int ks = 0; ks < 4; ks++) {
        const int base = (wrow + g) * APS + ks * 8 + t;
        Qh[ks][0] = sPh[base];           Ql[ks][0] = sPl[base];
        Qh[ks][1] = sPh[base + 8*APS];   Ql[ks][1] = sPl[base + 8*APS];
        Qh[ks][2] = sPh[base + 4];       Ql[ks][2] = sPl[base + 4];
        Qh[ks][3] = sPh[base + 8*APS+4]; Ql[ks][3] = sPl[base + 8*APS+4];
    }
    // each warp reads/writes only its own 16 sP rows from here on

    float oacc[8][4];
    #pragma unroll
    for (int nt = 0; nt < 8; nt++)
        #pragma unroll
        for (int r = 0; r < 4; r++) oacc[nt][r] = 0.f;
    float mrun[2] = {-INFINITY, -INFINITY};
    float lrun[2] = {0.f, 0.f};

    for (int kt = 0; kt < nkt; kt++) {
        if (kt + 1 < nkt) {
            attn_stage_load(sma, (kt + 1) & 1, kh, vh, kt + 1, tid);
            cp_commit();
            cp_wait<1>();
        } else {
            cp_wait<0>();
        }
        __syncthreads();

        if (kt * 64 <= qbase + wrow + 15) {
            uint32_t* stg = sma + A_KV + (kt & 1) * KV_STAGE;
            const uint32_t* pKh = stg + KV_KH;
            const uint32_t* pVh = stg + KV_VH;

            // ---- S = Q K^T ----
            float sacc[8][4];
            #pragma unroll
            for (int nt = 0; nt < 8; nt++)
                #pragma unroll
                for (int r = 0; r < 4; r++) sacc[nt][r] = 0.f;

            #pragma unroll
            for (int ks = 0; ks < 4; ks++) {
                #pragma unroll
                for (int nt = 0; nt < 8; nt++) {
                    const int bb = (nt * 8 + g) * APS + ks * 8 + t;
                    uint32_t bh2[2] = {pKh[bb], pKh[bb + 4]};
                    mma_f16(sacc[nt], Qh[ks], bh2);
                    mma_f16(sacc[nt], Ql[ks], bh2);
                }
            }

            // ---- masks + row max ----
            const bool diag = (kt * 64 + 63) > (qbase + wrow);
            float tmax[2] = {-INFINITY, -INFINITY};
            #pragma unroll
            for (int nt = 0; nt < 8; nt++) {
                #pragma unroll
                for (int e = 0; e < 4; e++) {
                    const int colL = nt * 8 + t * 2 + (e & 1);
                    float v = sacc[nt][e] + sMf[kt * 64 + colL];
                    if (diag) {
                        const int row = qbase + wrow + g + ((e >> 1) << 3);
                        const int col = kt * 64 + colL;
                        if (col > row) v = -INFINITY;
                    }
                    sacc[nt][e] = v;
                    tmax[e >> 1] = fmaxf(tmax[e >> 1], v);
                }
            }
            #pragma unroll
            for (int i = 0; i < 2; i++) {
                tmax[i] = fmaxf(tmax[i], __shfl_xor_sync(0xffffffff, tmax[i], 1));
                tmax[i] = fmaxf(tmax[i], __shfl_xor_sync(0xffffffff, tmax[i], 2));
            }

            // ---- online softmax ----
            float corr[2], psum[2] = {0.f, 0.f};
            #pragma unroll
            for (int i = 0; i < 2; i++) {
                float mnew = fmaxf(mrun[i], tmax[i]);
                corr[i] = __expf(mrun[i] - mnew);
                mrun[i] = mnew;
                lrun[i] *= corr[i];
            }
            #pragma unroll
            for (int nt = 0; nt < 8; nt++) {
                oacc[nt][0] *= corr[0]; oacc[nt][1] *= corr[0];
                oacc[nt][2] *= corr[1]; oacc[nt][3] *= corr[1];
            }
            #pragma unroll
            for (int nt = 0; nt < 8; nt++) {
                #pragma unroll
                for (int half = 0; half < 2; half++) {
                    float p0 = __expf(sacc[nt][half * 2 + 0] - mrun[half]);
                    float p1 = __expf(sacc[nt][half * 2 + 1] - mrun[half]);
                    psum[half] += p0 + p1;
                    float h0 = hhi(p0), h1 = hhi(p1);
                    const int row = wrow + g + half * 8;
                    sPh[row * APS + nt * 4 + t] = packh(h0, h1);
                    sPl[row * APS + nt * 4 + t] = packh(p0 - h0, p1 - h1);
                }
            }
            #pragma unroll
            for (int i = 0; i < 2; i++) {
                psum[i] += __shfl_xor_sync(0xffffffff, psum[i], 1);
                psum[i] += __shfl_xor_sync(0xffffffff, psum[i], 2);
                lrun[i] += psum[i];
            }
            __syncwarp();

            // ---- O += P V ----
            #pragma unroll
            for (int ks = 0; ks < 4; ks++) {
                uint32_t ah[4], al[4];
                const int abase = (wrow + g) * APS + ks * 8 + t;
                ah[0] = sPh[abase];             al[0] = sPl[abase];
                ah[1] = sPh[abase + 8*APS];     al[1] = sPl[abase + 8*APS];
                ah[2] = sPh[abase + 4];         al[2] = sPl[abase + 4];
                ah[3] = sPh[abase + 8*APS + 4]; al[3] = sPl[abase + 8*APS + 4];
                #pragma unroll
                for (int nt = 0; nt < 8; nt++) {
                    const int bb = (nt * 8 + g) * APS + ks * 8 + t;
                    uint32_t bh2[2] = {pVh[bb], pVh[bb + 4]};
                    mma_f16(oacc[nt], ah, bh2);
                    mma_f16(oacc[nt], al, bh2);
                }
            }
            __syncwarp();
        }
        __syncthreads();
    }

    // ---- epilogue: o/l, fp16 split, packed write ----
    const float inv0 = 1.f / lrun[0];
    const float inv1 = 1.f / lrun[1];
    const int r0 = qbase + wrow + g;
    const int r1 = r0 + 8;
    #pragma unroll
    for (int nt = 0; nt < 8; nt++) {
        float v0 = oacc[nt][0] * inv0, v1 = oacc[nt][1] * inv0;
        float v2 = oacc[nt][2] * inv1, v3 = oacc[nt][3] * inv1;
        const size_t o0 = (size_t)(b * S_ + r0) * 512 + h * 32 + nt * 4 + t;
        const size_t o1 = (size_t)(b * S_ + r1) * 512 + h * 32 + nt * 4 + t;
        float h0 = hhi(v0), h1 = hhi(v1), h2 = hhi(v2), h3 = hhi(v3);
        g_yhi[o0] = packh(h0, h1);
        g_ylo[o0] = packh(v0 - h0, v1 - h1);
        g_yhi[o1] = packh(h2, h3);
        g_ylo[o1] = packh(v2 - h2, v3 - h3);
    }
}

// ---------------- launch ----------------
extern "C" void kernel_launch(void* const* d_in, const int* in_sizes, int n_in,
                              void* d_out, int out_size)
{
    const float* x     = (const float*)d_in[0];
    const float* w_qkv = (const float*)d_in[1];
    const float* w_o   = (const float*)d_in[2];
    const int*   amask = (const int*)d_in[3];
    float* out = (float*)d_out;

    float* qkv_p;
    uint32_t *xhi, *xlo, *wqh, *woh, *yhi, *ylo;
    cudaGetSymbolAddress((void**)&qkv_p, g_qkv);
    cudaGetSymbolAddress((void**)&xhi, g_xhi);
    cudaGetSymbolAddress((void**)&xlo, g_xlo);
    cudaGetSymbolAddress((void**)&wqh, g_wqh);
    cudaGetSymbolAddress((void**)&woh, g_woh);
    cudaGetSymbolAddress((void**)&yhi, g_yhi);
    cudaGetSymbolAddress((void**)&ylo, g_ylo);

    const int smem_gemm = SMEM_GEMM_U32 * 4;
    cudaFuncSetAttribute(f16_gemm_kernel,
                         cudaFuncAttributeMaxDynamicSharedMemorySize, smem_gemm);
    const int smem_attn = SMEM_ATTN_U32 * 4;
    cudaFuncSetAttribute(attn_tc_kernel,
                         cudaFuncAttributeMaxDynamicSharedMemorySize, smem_attn);

    rope_table_kernel<<<256, 256>>>();

    split2_kernel<<<(B_*S_*D_/2 + 255) / 256, 256>>>(x, xhi, xlo, B_*S_*D_/2);
    wsplit_t_kernel<<<dim3(3*D_/32, D_/32), 256>>>(w_qkv, wqh, D_, 3*D_);
    wsplit_t_kernel<<<dim3(D_/32, D_/32), 256>>>(w_o, woh, D_, D_);

    // QKV = x @ w_qkv
    f16_gemm_kernel<<<dim3(3*D_/128, B_*S_/128), 256, smem_gemm>>>(
        xhi, xlo, wqh, qkv_p, B_*S_, 3*D_, D_);

    rope_split_kernel<<<B_*H_*(S_/32), 256>>>();

    attn_tc_kernel<<<(S_/128) * B_ * H_, 256, smem_attn>>>(amask);

    // out = y @ w_o
    f16_gemm_kernel<<<dim3(D_/128, B_*S_/128), 256, smem_gemm>>>(
        yhi, ylo, woh, out, B_*S_, D_, D_);
}

// round 8
// speedup vs baseline: 4.5278x; 1.0442x over previous
#include <cuda_runtime.h>
#include <cuda_fp16.h>
#include <math.h>
#include <stdint.h>

#define B_  2
#define S_  2048
#define D_  1024
#define H_  16
#define HD  64

// ---------------- scratch (device globals) ----------------
__device__ float g_qkv[B_*S_*3*D_];
__device__ float g_cos[S_*32];
__device__ float g_sin[S_*32];
// fp16 packed pairs-along-K as uint32. A-side: hi+lo. B-side: hi only.
__device__ uint32_t g_xhi[B_*S_*D_/2],  g_xlo[B_*S_*D_/2];
__device__ uint32_t g_wqh[3*D_*D_/2];                       // transposed [N][K]
__device__ uint32_t g_woh[D_*D_/2];                         // transposed [N][K]
__device__ uint32_t g_qhi[B_*H_*S_*HD/2], g_qlo[B_*H_*S_*HD/2];
__device__ uint32_t g_khi[B_*H_*S_*HD/2];
__device__ uint32_t g_vthi[B_*H_*HD*S_/2];                  // V transposed [d][S]
__device__ uint32_t g_yhi[B_*S_*D_/2],  g_ylo[B_*S_*D_/2];

// ---------------- helpers ----------------
__device__ __forceinline__ float hhi(float v) {
    return __half2float(__float2half_rn(v));
}
__device__ __forceinline__ uint32_t packh(float f_low, float f_high) {
    uint32_t r;
    asm("cvt.rn.f16x2.f32 %0, %1, %2;" : "=r"(r) : "f"(f_high), "f"(f_low));
    return r;
}
__device__ __forceinline__ float fexp2(float x) {
    float r;
    asm("ex2.approx.f32 %0, %1;" : "=f"(r) : "f"(x));
    return r;
}
__device__ __forceinline__ void cp16(void* dst, const void* src) {
    uint32_t d = (uint32_t)__cvta_generic_to_shared(dst);
    asm volatile("cp.async.cg.shared.global [%0], [%1], 16;\n" :: "r"(d), "l"(src));
}
__device__ __forceinline__ void cp_commit() {
    asm volatile("cp.async.commit_group;\n");
}
template<int N> __device__ __forceinline__ void cp_wait() {
    asm volatile("cp.async.wait_group %0;\n" :: "n"(N));
}
__device__ __forceinline__ void mma_f16(float* d, const uint32_t* a, const uint32_t* b) {
    asm volatile(
        "mma.sync.aligned.m16n8k16.row.col.f32.f16.f16.f32 "
        "{%0,%1,%2,%3}, {%4,%5,%6,%7}, {%8,%9}, {%0,%1,%2,%3};\n"
        : "+f"(d[0]), "+f"(d[1]), "+f"(d[2]), "+f"(d[3])
        : "r"(a[0]), "r"(a[1]), "r"(a[2]), "r"(a[3]), "r"(b[0]), "r"(b[1]));
}
__device__ __forceinline__ void ldsm4(uint32_t* r, uint32_t saddr) {
    asm volatile("ldmatrix.sync.aligned.m8n8.x4.shared.b16 {%0,%1,%2,%3}, [%4];"
        : "=r"(r[0]), "=r"(r[1]), "=r"(r[2]), "=r"(r[3]) : "r"(saddr));
}

// ---------------- RoPE table ----------------
__global__ void rope_table_kernel() {
    int idx = blockIdx.x * 256 + threadIdx.x;
    if (idx >= S_ * 32) return;
    int s = idx >> 5;
    int j = idx & 31;
    double inv = pow(10000.0, -((double)(2 * j)) / 64.0);
    double ang = (double)s * inv;
    g_cos[idx] = (float)cos(ang);
    g_sin[idx] = (float)sin(ang);
}

// ---------------- elementwise fp16 hi/lo split (packed pairs) ----------------
__global__ __launch_bounds__(256) void split2_kernel(
    const float* __restrict__ src, uint32_t* __restrict__ hi, uint32_t* __restrict__ lo, int n2)
{
    int i = blockIdx.x * 256 + threadIdx.x;
    if (i >= n2) return;
    float2 v = ((const float2*)src)[i];
    float h0 = hhi(v.x), h1 = hhi(v.y);
    hi[i] = packh(h0, h1);
    lo[i] = packh(v.x - h0, v.y - h1);
}

// ---------------- weight transpose + fp16 quantize: w[K][N] -> wt[N][K] ----------------
__global__ __launch_bounds__(256) void wsplit_t_kernel(
    const float* __restrict__ w, uint32_t* __restrict__ th, int Kd, int Nd)
{
    __shared__ float tile[32][33];
    int n0 = blockIdx.x * 32, k0 = blockIdx.y * 32;
    int tx = threadIdx.x & 31, ty = threadIdx.x >> 5;
    #pragma unroll
    for (int r = 0; r < 32; r += 8)
        tile[ty + r][tx] = w[(size_t)(k0 + ty + r) * Nd + n0 + tx];
    __syncthreads();
    __half* thb = (__half*)th;
    #pragma unroll
    for (int r = 0; r < 32; r += 8) {
        int n = n0 + ty + r, k = k0 + tx;
        thb[(size_t)n * Kd + k] = __float2half_rn(tile[tx][ty + r]);
    }
}

// ---------------- RoPE + transpose + fp16 split (log2e folded into q scale) ----------------
__global__ __launch_bounds__(256) void rope_split_kernel() {
    __shared__ float vt[64][33];
    const int blk = blockIdx.x;
    const int bh = blk >> 6;
    const int stile = (blk & 63) * 32;
    const int b = bh >> 4, h = bh & 15;
    const int tid = threadIdx.x;
    const int i = tid & 63, sl0 = tid >> 6;

    __half* qhb = (__half*)g_qhi;
    __half* qlb = (__half*)g_qlo;
    __half* khb = (__half*)g_khi;

    const float QSC = 0.125f * 1.44269504088896340736f;  // 1/sqrt(64) * log2(e)

    for (int sl = sl0; sl < 32; sl += 4) {
        int s = stile + sl;
        const float* row = g_qkv + (size_t)(b * S_ + s) * 3 * D_;
        int j = i & 31;
        float c  = g_cos[s * 32 + j];
        float sn = g_sin[s * 32 + j];
        float qv = row[h * 64 + i];
        float qp = row[h * 64 + (i ^ 32)];
        float kv = row[D_ + h * 64 + i];
        float kp = row[D_ + h * 64 + (i ^ 32)];
        float vv = row[2 * D_ + h * 64 + i];
        float sg = (i < 32) ? -1.f : 1.f;
        float qo = (qv * c + sg * qp * sn) * QSC;
        float ko = kv * c + sg * kp * sn;
        size_t o = ((size_t)bh * S_ + s) * HD + i;
        float qh = hhi(qo);
        qhb[o] = __float2half_rn(qh);
        qlb[o] = __float2half_rn(qo - qh);
        khb[o] = __float2half_rn(ko);
        vt[i][sl] = vv;
    }
    __syncthreads();
    const int d = tid >> 2, p = tid & 3;
    uint32_t oh[4];
    #pragma unroll
    for (int e = 0; e < 4; e++) {
        int s0 = p * 8 + e * 2;
        oh[e] = packh(vt[d][s0], vt[d][s0 + 1]);
    }
    size_t vo = (size_t)bh * HD * (S_/2) + (size_t)d * (S_/2) + (stile >> 1) + p * 4;
    *(uint4*)&g_vthi[vo] = *(uint4*)oh;
}

// ---------------- fp16 2-product GEMM with ldmatrix frag loads ----------------
#define KS 20
#define G_AH 0
#define G_AL 2560
#define G_BH 5120
#define G_STAGE 7680
#define SMEM_GEMM_U32 (2*G_STAGE)

__device__ __forceinline__ void gemm_stage_load(
    uint32_t* st, const uint32_t* Ah, const uint32_t* Al, const uint32_t* Bh,
    int kp0, int tid, int Kp)
{
    const int row = tid >> 1;
    const int c = (tid & 1) * 8;
    const size_t ga = (size_t)row * Kp + kp0 + c;
    cp16(&st[G_AH + row * KS + c],     Ah + ga);
    cp16(&st[G_AH + row * KS + c + 4], Ah + ga + 4);
    cp16(&st[G_AL + row * KS + c],     Al + ga);
    cp16(&st[G_AL + row * KS + c + 4], Al + ga + 4);
    cp16(&st[G_BH + row * KS + c],     Bh + ga);
    cp16(&st[G_BH + row * KS + c + 4], Bh + ga + 4);
}

__global__ __launch_bounds__(256, 2) void f16_gemm_kernel(
    const uint32_t* __restrict__ Ahi, const uint32_t* __restrict__ Alo,
    const uint32_t* __restrict__ Bhi,
    float* __restrict__ C, int M, int N, int K)
{
    extern __shared__ uint32_t smg[];
    const int Kp = K >> 1;
    const int tid  = threadIdx.x;
    const int warp = tid >> 5;
    const int lane = tid & 31;
    const int g = lane >> 2;
    const int t = lane & 3;
    const int mBase = (warp >> 1) * 32;
    const int nBase = (warp & 1) * 64;

    // ldmatrix per-lane offsets
    const int r8 = lane & 7;
    const int aR = ((lane >> 3) & 1) * 8 + r8;     // A row-in-frag
    const int aC = ((lane >> 4) & 1) * 4;          // A col pairs
    const int bR = ((lane >> 4) & 1) * 8 + r8;     // B row-in-frag (2 n-tiles)
    const int bC = ((lane >> 3) & 1) * 4;
    const uint32_t smB = (uint32_t)__cvta_generic_to_shared(smg);

    Ahi += (size_t)blockIdx.y * 128 * Kp;
    Alo += (size_t)blockIdx.y * 128 * Kp;
    Bhi += (size_t)blockIdx.x * 128 * Kp;

    float acc[2][8][4];
    #pragma unroll
    for (int mt = 0; mt < 2; mt++)
        #pragma unroll
        for (int nt = 0; nt < 8; nt++)
            #pragma unroll
            for (int r = 0; r < 4; r++) acc[mt][nt][r] = 0.f;

    const int NT = Kp / 16;
    gemm_stage_load(smg, Ahi, Alo, Bhi, 0, tid, Kp);
    cp_commit();

    for (int it = 0; it < NT; it++) {
        if (it + 1 < NT) {
            gemm_stage_load(smg + ((it + 1) & 1) * G_STAGE, Ahi, Alo, Bhi,
                            (it + 1) * 16, tid, Kp);
            cp_commit();
            cp_wait<1>();
        } else {
            cp_wait<0>();
        }
        __syncthreads();

        const uint32_t stB = smB + ((it & 1) * G_STAGE) * 4;
        #pragma unroll
        for (int kstep = 0; kstep < 2; kstep++) {
            const int k8 = kstep * 8;
            uint32_t ah[2][4], al[2][4];
            #pragma unroll
            for (int mt = 0; mt < 2; mt++) {
                const uint32_t abase = stB + ((G_AH + (mBase + mt * 16 + aR) * KS + k8 + aC) << 2);
                ldsm4(ah[mt], abase);
                ldsm4(al[mt], abase + (G_AL - G_AH) * 4);
            }
            #pragma unroll
            for (int ntp = 0; ntp < 4; ntp++) {
                uint32_t bb[4];
                ldsm4(bb, stB + ((G_BH + (nBase + ntp * 16 + bR) * KS + k8 + bC) << 2));
                #pragma unroll
                for (int mt = 0; mt < 2; mt++) {
                    mma_f16(acc[mt][2 * ntp],     ah[mt], bb);
                    mma_f16(acc[mt][2 * ntp],     al[mt], bb);
                    mma_f16(acc[mt][2 * ntp + 1], ah[mt], bb + 2);
                    mma_f16(acc[mt][2 * ntp + 1], al[mt], bb + 2);
                }
            }
        }
        __syncthreads();
    }

    C += (size_t)blockIdx.y * 128 * N + blockIdx.x * 128;
    #pragma unroll
    for (int mt = 0; mt < 2; mt++) {
        const int r0 = mBase + mt * 16 + g;
        #pragma unroll
        for (int nt = 0; nt < 8; nt++) {
            const int c = nBase + nt * 8 + t * 2;
            *(float2*)&C[(size_t)r0 * N + c]       = make_float2(acc[mt][nt][0], acc[mt][nt][1]);
            *(float2*)&C[(size_t)(r0 + 8) * N + c] = make_float2(acc[mt][nt][2], acc[mt][nt][3]);
        }
    }
}

// ---------------- fp16 tensor-core causal flash attention (ldmatrix + ex2) ----------------
#define APS 36
#define A_PH 0
#define A_PL 4608
#define A_KV 9216
#define KV_KH 0
#define KV_VH 2304
#define KV_STAGE 4608
#define A_MSK (A_KV + 2*KV_STAGE)
#define SMEM_ATTN_U32 (A_MSK + S_)

__device__ __forceinline__ void attn_stage_load(
    uint32_t* sma, int st, const uint32_t* kh, const uint32_t* vh, int kt, int tid)
{
    uint32_t* base = sma + A_KV + st * KV_STAGE;
    const int r = tid >> 2, c = tid & 3;
    const size_t gk = (size_t)(kt * 64 + r) * 32;
    cp16(&base[KV_KH + r * APS + c * 4],       kh + gk + c * 4);
    cp16(&base[KV_KH + r * APS + (c + 4) * 4], kh + gk + (c + 4) * 4);
    const size_t gv = (size_t)r * (S_/2) + kt * 32;
    cp16(&base[KV_VH + r * APS + c * 4],       vh + gv + c * 4);
    cp16(&base[KV_VH + r * APS + (c + 4) * 4], vh + gv + (c + 4) * 4);
}

__global__ __launch_bounds__(256, 1) void attn_tc_kernel(const int* __restrict__ amask) {
    extern __shared__ uint32_t sma[];
    uint32_t* sPh = sma + A_PH;
    uint32_t* sPl = sma + A_PL;
    float* sMf = (float*)(sma + A_MSK);

    const int tid  = threadIdx.x;
    const int warp = tid >> 5;
    const int lane = tid & 31;
    const int g = lane >> 2;
    const int t = lane & 3;
    // LPT ordering: heaviest q-tiles first
    const int qtile = (S_ / 128 - 1) - (int)(blockIdx.x >> 5);
    const int bh    = blockIdx.x & 31;
    const int b  = bh >> 4;
    const int h  = bh & 15;
    const int qbase = qtile * 128;
    const int wrow  = warp * 16;

    // ldmatrix per-lane offsets
    const int r8 = lane & 7;
    const int aR = ((lane >> 3) & 1) * 8 + r8;
    const int aC = ((lane >> 4) & 1) * 4;
    const int bR = ((lane >> 4) & 1) * 8 + r8;
    const int bC = ((lane >> 3) & 1) * 4;
    const uint32_t smB = (uint32_t)__cvta_generic_to_shared(sma);

    const uint32_t* kh = g_khi + (size_t)bh * S_ * 32;
    const uint32_t* vh = g_vthi + (size_t)bh * HD * (S_/2);

    const int nkt = (qbase + 128) / 64;

    attn_stage_load(sma, 0, kh, vh, 0, tid);
    cp_commit();

    {
        const uint32_t* qgh = g_qhi + ((size_t)bh * S_ + qbase) * 32;
        const uint32_t* qgl = g_qlo + ((size_t)bh * S_ + qbase) * 32;
        for (int idx = tid; idx < 1024; idx += 256) {
            int r = idx >> 3, c4 = (idx & 7) * 4;
            *(uint4*)&sPh[r * APS + c4] = *(const uint4*)(qgh + r * 32 + c4);
            *(uint4*)&sPl[r * APS + c4] = *(const uint4*)(qgl + r * 32 + c4);
        }
        for (int idx = tid; idx < S_; idx += 256)
            sMf[idx] = (amask[b * S_ + idx] == 0) ? -INFINITY : 0.f;
    }
    __syncthreads();

    uint32_t Qh[4][4], Ql[4][4];
    #pragma unroll
    for (int ks = 0; ks < 4; ks++) {
        const uint32_t qaddr = smB + (((wrow + aR) * APS + ks * 8 + aC) << 2);
        ldsm4(Qh[ks], qaddr);
        ldsm4(Ql[ks], qaddr + A_PL * 4);
    }
    // each warp reads/writes only its own 16 sP rows from here on

    float oacc[8][4];
    #pragma unroll
    for (int nt = 0; nt < 8; nt++)
        #pragma unroll
        for (int r = 0; r < 4; r++) oacc[nt][r] = 0.f;
    float mrun[2] = {-INFINITY, -INFINITY};
    float lrun[2] = {0.f, 0.f};

    for (int kt = 0; kt < nkt; kt++) {
        if (kt + 1 < nkt) {
            attn_stage_load(sma, (kt + 1) & 1, kh, vh, kt + 1, tid);
            cp_commit();
            cp_wait<1>();
        } else {
            cp_wait<0>();
        }
        __syncthreads();

        if (kt * 64 <= qbase + wrow + 15) {
            const uint32_t kvB = smB + ((A_KV + (kt & 1) * KV_STAGE) << 2);

            // ---- S = Q K^T ----
            float sacc[8][4];
            #pragma unroll
            for (int nt = 0; nt < 8; nt++)
                #pragma unroll
                for (int r = 0; r < 4; r++) sacc[nt][r] = 0.f;

            #pragma unroll
            for (int ks = 0; ks < 4; ks++) {
                #pragma unroll
                for (int ntp = 0; ntp < 4; ntp++) {
                    uint32_t bb[4];
                    ldsm4(bb, kvB + ((KV_KH + (ntp * 16 + bR) * APS + ks * 8 + bC) << 2));
                    mma_f16(sacc[2 * ntp],     Qh[ks], bb);
                    mma_f16(sacc[2 * ntp],     Ql[ks], bb);
                    mma_f16(sacc[2 * ntp + 1], Qh[ks], bb + 2);
                    mma_f16(sacc[2 * ntp + 1], Ql[ks], bb + 2);
                }
            }

            // ---- masks + row max (log2 domain) ----
            const bool diag = (kt * 64 + 63) > (qbase + wrow);
            float tmax[2] = {-INFINITY, -INFINITY};
            #pragma unroll
            for (int nt = 0; nt < 8; nt++) {
                #pragma unroll
                for (int e = 0; e < 4; e++) {
                    const int colL = nt * 8 + t * 2 + (e & 1);
                    float v = sacc[nt][e] + sMf[kt * 64 + colL];
                    if (diag) {
                        const int row = qbase + wrow + g + ((e >> 1) << 3);
                        const int col = kt * 64 + colL;
                        if (col > row) v = -INFINITY;
                    }
                    sacc[nt][e] = v;
                    tmax[e >> 1] = fmaxf(tmax[e >> 1], v);
                }
            }
            #pragma unroll
            for (int i = 0; i < 2; i++) {
                tmax[i] = fmaxf(tmax[i], __shfl_xor_sync(0xffffffff, tmax[i], 1));
                tmax[i] = fmaxf(tmax[i], __shfl_xor_sync(0xffffffff, tmax[i], 2));
            }

            // ---- online softmax (base-2) ----
            float corr[2], psum[2] = {0.f, 0.f};
            #pragma unroll
            for (int i = 0; i < 2; i++) {
                float mnew = fmaxf(mrun[i], tmax[i]);
                corr[i] = fexp2(mrun[i] - mnew);
                mrun[i] = mnew;
                lrun[i] *= corr[i];
            }
            #pragma unroll
            for (int nt = 0; nt < 8; nt++) {
                oacc[nt][0] *= corr[0]; oacc[nt][1] *= corr[0];
                oacc[nt][2] *= corr[1]; oacc[nt][3] *= corr[1];
            }
            #pragma unroll
            for (int nt = 0; nt < 8; nt++) {
                #pragma unroll
                for (int half = 0; half < 2; half++) {
                    float p0 = fexp2(sacc[nt][half * 2 + 0] - mrun[half]);
                    float p1 = fexp2(sacc[nt][half * 2 + 1] - mrun[half]);
                    psum[half] += p0 + p1;
                    float h0 = hhi(p0), h1 = hhi(p1);
                    const int row = wrow + g + half * 8;
                    sPh[row * APS + nt * 4 + t] = packh(h0, h1);
                    sPl[row * APS + nt * 4 + t] = packh(p0 - h0, p1 - h1);
                }
            }
            #pragma unroll
            for (int i = 0; i < 2; i++) {
                psum[i] += __shfl_xor_sync(0xffffffff, psum[i], 1);
                psum[i] += __shfl_xor_sync(0xffffffff, psum[i], 2);
                lrun[i] += psum[i];
            }
            __syncwarp();

            // ---- O += P V ----
            #pragma unroll
            for (int ks = 0; ks < 4; ks++) {
                uint32_t ph4[4], pl4[4];
                const uint32_t paddr = smB + (((wrow + aR) * APS + ks * 8 + aC) << 2);
                ldsm4(ph4, paddr);
                ldsm4(pl4, paddr + A_PL * 4);
                #pragma unroll
                for (int ntp = 0; ntp < 4; ntp++) {
                    uint32_t vv[4];
                    ldsm4(vv, kvB + ((KV_VH + (ntp * 16 + bR) * APS + ks * 8 + bC) << 2));
                    mma_f16(oacc[2 * ntp],     ph4, vv);
                    mma_f16(oacc[2 * ntp],     pl4, vv);
                    mma_f16(oacc[2 * ntp + 1], ph4, vv + 2);
                    mma_f16(oacc[2 * ntp + 1], pl4, vv + 2);
                }
            }
            __syncwarp();
        }
        __syncthreads();
    }

    // ---- epilogue: o/l, fp16 split, packed write ----
    const float inv0 = 1.f / lrun[0];
    const float inv1 = 1.f / lrun[1];
    const int r0 = qbase + wrow + g;
    const int r1 = r0 + 8;
    #pragma unroll
    for (int nt = 0; nt < 8; nt++) {
        float v0 = oacc[nt][0] * inv0, v1 = oacc[nt][1] * inv0;
        float v2 = oacc[nt][2] * inv1, v3 = oacc[nt][3] * inv1;
        const size_t o0 = (size_t)(b * S_ + r0) * 512 + h * 32 + nt * 4 + t;
        const size_t o1 = (size_t)(b * S_ + r1) * 512 + h * 32 + nt * 4 + t;
        float h0 = hhi(v0), h1 = hhi(v1), h2 = hhi(v2), h3 = hhi(v3);
        g_yhi[o0] = packh(h0, h1);
        g_ylo[o0] = packh(v0 - h0, v1 - h1);
        g_yhi[o1] = packh(h2, h3);
        g_ylo[o1] = packh(v2 - h2, v3 - h3);
    }
}

// ---------------- launch ----------------
extern "C" void kernel_launch(void* const* d_in, const int* in_sizes, int n_in,
                              void* d_out, int out_size)
{
    const float* x     = (const float*)d_in[0];
    const float* w_qkv = (const float*)d_in[1];
    const float* w_o   = (const float*)d_in[2];
    const int*   amask = (const int*)d_in[3];
    float* out = (float*)d_out;

    float* qkv_p;
    uint32_t *xhi, *xlo, *wqh, *woh, *yhi, *ylo;
    cudaGetSymbolAddress((void**)&qkv_p, g_qkv);
    cudaGetSymbolAddress((void**)&xhi, g_xhi);
    cudaGetSymbolAddress((void**)&xlo, g_xlo);
    cudaGetSymbolAddress((void**)&wqh, g_wqh);
    cudaGetSymbolAddress((void**)&woh, g_woh);
    cudaGetSymbolAddress((void**)&yhi, g_yhi);
    cudaGetSymbolAddress((void**)&ylo, g_ylo);

    const int smem_gemm = SMEM_GEMM_U32 * 4;
    cudaFuncSetAttribute(f16_gemm_kernel,
                         cudaFuncAttributeMaxDynamicSharedMemorySize, smem_gemm);
    const int smem_attn = SMEM_ATTN_U32 * 4;
    cudaFuncSetAttribute(attn_tc_kernel,
                         cudaFuncAttributeMaxDynamicSharedMemorySize, smem_attn);

    rope_table_kernel<<<256, 256>>>();

    split2_kernel<<<(B_*S_*D_/2 + 255) / 256, 256>>>(x, xhi, xlo, B_*S_*D_/2);
    wsplit_t_kernel<<<dim3(3*D_/32, D_/32), 256>>>(w_qkv, wqh, D_, 3*D_);
    wsplit_t_kernel<<<dim3(D_/32, D_/32), 256>>>(w_o, woh, D_, D_);

    // QKV = x @ w_qkv
    f16_gemm_kernel<<<dim3(3*D_/128, B_*S_/128), 256, smem_gemm>>>(
        xhi, xlo, wqh, qkv_p, B_*S_, 3*D_, D_);

    rope_split_kernel<<<B_*H_*(S_/32), 256>>>();

    attn_tc_kernel<<<(S_/128) * B_ * H_, 256, smem_attn>>>(amask);

    // out = y @ w_o
    f16_gemm_kernel<<<dim3(D_/128, B_*S_/128), 256, smem_gemm>>>(
        yhi, ylo, woh, out, B_*S_, D_, D_);
}

// round 9
// speedup vs baseline: 4.8486x; 1.0709x over previous
#include <cuda_runtime.h>
#include <cuda_fp16.h>
#include <math.h>
#include <stdint.h>

#define B_  2
#define S_  2048
#define D_  1024
#define H_  16
#define HD  64

// ---------------- scratch (device globals) ----------------
__device__ float g_qkv[B_*S_*3*D_];
__device__ float g_cos[S_*32];
__device__ float g_sin[S_*32];
// fp16 packed pairs-along-K as uint32. A-side: hi+lo. B-side: hi only.
__device__ uint32_t g_xhi[B_*S_*D_/2],  g_xlo[B_*S_*D_/2];
__device__ uint32_t g_wqh[3*D_*D_/2];                       // transposed [N][K]
__device__ uint32_t g_woh[D_*D_/2];                         // transposed [N][K]
__device__ uint32_t g_qhi[B_*H_*S_*HD/2], g_qlo[B_*H_*S_*HD/2];
__device__ uint32_t g_khi[B_*H_*S_*HD/2];
__device__ uint32_t g_vthi[B_*H_*HD*S_/2];                  // V transposed [d][S]
__device__ uint32_t g_yhi[B_*S_*D_/2],  g_ylo[B_*S_*D_/2];

// ---------------- helpers ----------------
__device__ __forceinline__ float hhi(float v) {
    return __half2float(__float2half_rn(v));
}
__device__ __forceinline__ uint32_t packh(float f_low, float f_high) {
    uint32_t r;
    asm("cvt.rn.f16x2.f32 %0, %1, %2;" : "=r"(r) : "f"(f_high), "f"(f_low));
    return r;
}
__device__ __forceinline__ float fexp2(float x) {
    float r;
    asm("ex2.approx.f32 %0, %1;" : "=f"(r) : "f"(x));
    return r;
}
__device__ __forceinline__ void cp16(void* dst, const void* src) {
    uint32_t d = (uint32_t)__cvta_generic_to_shared(dst);
    asm volatile("cp.async.cg.shared.global [%0], [%1], 16;\n" :: "r"(d), "l"(src));
}
__device__ __forceinline__ void cp_commit() {
    asm volatile("cp.async.commit_group;\n");
}
template<int N> __device__ __forceinline__ void cp_wait() {
    asm volatile("cp.async.wait_group %0;\n" :: "n"(N));
}
__device__ __forceinline__ void mma_f16(float* d, const uint32_t* a, const uint32_t* b) {
    asm volatile(
        "mma.sync.aligned.m16n8k16.row.col.f32.f16.f16.f32 "
        "{%0,%1,%2,%3}, {%4,%5,%6,%7}, {%8,%9}, {%0,%1,%2,%3};\n"
        : "+f"(d[0]), "+f"(d[1]), "+f"(d[2]), "+f"(d[3])
        : "r"(a[0]), "r"(a[1]), "r"(a[2]), "r"(a[3]), "r"(b[0]), "r"(b[1]));
}
__device__ __forceinline__ void ldsm4(uint32_t* r, uint32_t saddr) {
    asm volatile("ldmatrix.sync.aligned.m8n8.x4.shared.b16 {%0,%1,%2,%3}, [%4];"
        : "=r"(r[0]), "=r"(r[1]), "=r"(r[2]), "=r"(r[3]) : "r"(saddr));
}

// ---------------- RoPE table ----------------
__global__ void rope_table_kernel() {
    int idx = blockIdx.x * 256 + threadIdx.x;
    if (idx >= S_ * 32) return;
    int s = idx >> 5;
    int j = idx & 31;
    double inv = pow(10000.0, -((double)(2 * j)) / 64.0);
    double ang = (double)s * inv;
    g_cos[idx] = (float)cos(ang);
    g_sin[idx] = (float)sin(ang);
}

// ---------------- elementwise fp16 hi/lo split (packed pairs) ----------------
__global__ __launch_bounds__(256) void split2_kernel(
    const float* __restrict__ src, uint32_t* __restrict__ hi, uint32_t* __restrict__ lo, int n2)
{
    int i = blockIdx.x * 256 + threadIdx.x;
    if (i >= n2) return;
    float2 v = ((const float2*)src)[i];
    float h0 = hhi(v.x), h1 = hhi(v.y);
    hi[i] = packh(h0, h1);
    lo[i] = packh(v.x - h0, v.y - h1);
}

// ---------------- weight transpose + fp16 quantize: w[K][N] -> wt[N][K] ----------------
__global__ __launch_bounds__(256) void wsplit_t_kernel(
    const float* __restrict__ w, uint32_t* __restrict__ th, int Kd, int Nd)
{
    __shared__ float tile[32][33];
    int n0 = blockIdx.x * 32, k0 = blockIdx.y * 32;
    int tx = threadIdx.x & 31, ty = threadIdx.x >> 5;
    #pragma unroll
    for (int r = 0; r < 32; r += 8)
        tile[ty + r][tx] = w[(size_t)(k0 + ty + r) * Nd + n0 + tx];
    __syncthreads();
    __half* thb = (__half*)th;
    #pragma unroll
    for (int r = 0; r < 32; r += 8) {
        int n = n0 + ty + r, k = k0 + tx;
        thb[(size_t)n * Kd + k] = __float2half_rn(tile[tx][ty + r]);
    }
}

// ---------------- RoPE + transpose + fp16 split (log2e folded into q scale) ----------------
__global__ __launch_bounds__(256) void rope_split_kernel() {
    __shared__ float vt[64][33];
    const int blk = blockIdx.x;
    const int bh = blk >> 6;
    const int stile = (blk & 63) * 32;
    const int b = bh >> 4, h = bh & 15;
    const int tid = threadIdx.x;
    const int i = tid & 63, sl0 = tid >> 6;

    __half* qhb = (__half*)g_qhi;
    __half* qlb = (__half*)g_qlo;
    __half* khb = (__half*)g_khi;

    const float QSC = 0.125f * 1.44269504088896340736f;  // 1/sqrt(64) * log2(e)

    for (int sl = sl0; sl < 32; sl += 4) {
        int s = stile + sl;
        const float* row = g_qkv + (size_t)(b * S_ + s) * 3 * D_;
        int j = i & 31;
        float c  = g_cos[s * 32 + j];
        float sn = g_sin[s * 32 + j];
        float qv = row[h * 64 + i];
        float qp = row[h * 64 + (i ^ 32)];
        float kv = row[D_ + h * 64 + i];
        float kp = row[D_ + h * 64 + (i ^ 32)];
        float vv = row[2 * D_ + h * 64 + i];
        float sg = (i < 32) ? -1.f : 1.f;
        float qo = (qv * c + sg * qp * sn) * QSC;
        float ko = kv * c + sg * kp * sn;
        size_t o = ((size_t)bh * S_ + s) * HD + i;
        float qh = hhi(qo);
        qhb[o] = __float2half_rn(qh);
        qlb[o] = __float2half_rn(qo - qh);
        khb[o] = __float2half_rn(ko);
        vt[i][sl] = vv;
    }
    __syncthreads();
    const int d = tid >> 2, p = tid & 3;
    uint32_t oh[4];
    #pragma unroll
    for (int e = 0; e < 4; e++) {
        int s0 = p * 8 + e * 2;
        oh[e] = packh(vt[d][s0], vt[d][s0 + 1]);
    }
    size_t vo = (size_t)bh * HD * (S_/2) + (size_t)d * (S_/2) + (stile >> 1) + p * 4;
    *(uint4*)&g_vthi[vo] = *(uint4*)oh;
}

// ---------------- fp16 2-product GEMM, 3-stage cp.async, ldmatrix ----------------
#define KS 20
#define G_AH 0
#define G_AL 2560
#define G_BH 5120
#define G_STAGE 7680
#define SMEM_GEMM_U32 (3*G_STAGE)

__device__ __forceinline__ void gemm_stage_load(
    uint32_t* st, const uint32_t* Ah, const uint32_t* Al, const uint32_t* Bh,
    int kp0, int tid, int Kp)
{
    const int row = tid >> 1;
    const int c = (tid & 1) * 8;
    const size_t ga = (size_t)row * Kp + kp0 + c;
    cp16(&st[G_AH + row * KS + c],     Ah + ga);
    cp16(&st[G_AH + row * KS + c + 4], Ah + ga + 4);
    cp16(&st[G_AL + row * KS + c],     Al + ga);
    cp16(&st[G_AL + row * KS + c + 4], Al + ga + 4);
    cp16(&st[G_BH + row * KS + c],     Bh + ga);
    cp16(&st[G_BH + row * KS + c + 4], Bh + ga + 4);
}

__global__ __launch_bounds__(256, 2) void f16_gemm_kernel(
    const uint32_t* __restrict__ Ahi, const uint32_t* __restrict__ Alo,
    const uint32_t* __restrict__ Bhi,
    float* __restrict__ C, int M, int N, int K)
{
    extern __shared__ uint32_t smg[];
    const int Kp = K >> 1;
    const int tid  = threadIdx.x;
    const int warp = tid >> 5;
    const int lane = tid & 31;
    const int g = lane >> 2;
    const int t = lane & 3;
    const int mBase = (warp >> 1) * 32;
    const int nBase = (warp & 1) * 64;

    const int r8 = lane & 7;
    const int aR = ((lane >> 3) & 1) * 8 + r8;
    const int aC = ((lane >> 4) & 1) * 4;
    const int bR = ((lane >> 4) & 1) * 8 + r8;
    const int bC = ((lane >> 3) & 1) * 4;
    const uint32_t smB = (uint32_t)__cvta_generic_to_shared(smg);

    Ahi += (size_t)blockIdx.y * 128 * Kp;
    Alo += (size_t)blockIdx.y * 128 * Kp;
    Bhi += (size_t)blockIdx.x * 128 * Kp;

    float acc[2][8][4];
    #pragma unroll
    for (int mt = 0; mt < 2; mt++)
        #pragma unroll
        for (int nt = 0; nt < 8; nt++)
            #pragma unroll
            for (int r = 0; r < 4; r++) acc[mt][nt][r] = 0.f;

    const int NT = Kp / 16;
    gemm_stage_load(smg, Ahi, Alo, Bhi, 0, tid, Kp);
    cp_commit();
    gemm_stage_load(smg + G_STAGE, Ahi, Alo, Bhi, 16, tid, Kp);
    cp_commit();

    int stage = 0;
    for (int it = 0; it < NT; it++) {
        cp_wait<1>();
        __syncthreads();

        // prefetch it+2 into the buffer freed by compute(it-1) (guarded by barrier above)
        if (it + 2 < NT) {
            int s2 = stage + 2; if (s2 >= 3) s2 -= 3;
            gemm_stage_load(smg + s2 * G_STAGE, Ahi, Alo, Bhi, (it + 2) * 16, tid, Kp);
        }
        cp_commit();   // always commit (possibly empty) to keep wait<1> bookkeeping exact

        const uint32_t stB = smB + (stage * G_STAGE) * 4;
        #pragma unroll
        for (int kstep = 0; kstep < 2; kstep++) {
            const int k8 = kstep * 8;
            uint32_t ah[2][4], al[2][4];
            #pragma unroll
            for (int mt = 0; mt < 2; mt++) {
                const uint32_t abase = stB + ((G_AH + (mBase + mt * 16 + aR) * KS + k8 + aC) << 2);
                ldsm4(ah[mt], abase);
                ldsm4(al[mt], abase + (G_AL - G_AH) * 4);
            }
            #pragma unroll
            for (int ntp = 0; ntp < 4; ntp++) {
                uint32_t bb[4];
                ldsm4(bb, stB + ((G_BH + (nBase + ntp * 16 + bR) * KS + k8 + bC) << 2));
                #pragma unroll
                for (int mt = 0; mt < 2; mt++) {
                    mma_f16(acc[mt][2 * ntp],     ah[mt], bb);
                    mma_f16(acc[mt][2 * ntp],     al[mt], bb);
                    mma_f16(acc[mt][2 * ntp + 1], ah[mt], bb + 2);
                    mma_f16(acc[mt][2 * ntp + 1], al[mt], bb + 2);
                }
            }
        }
        if (++stage == 3) stage = 0;
    }

    C += (size_t)blockIdx.y * 128 * N + blockIdx.x * 128;
    #pragma unroll
    for (int mt = 0; mt < 2; mt++) {
        const int r0 = mBase + mt * 16 + g;
        #pragma unroll
        for (int nt = 0; nt < 8; nt++) {
            const int c = nBase + nt * 8 + t * 2;
            *(float2*)&C[(size_t)r0 * N + c]       = make_float2(acc[mt][nt][0], acc[mt][nt][1]);
            *(float2*)&C[(size_t)(r0 + 8) * N + c] = make_float2(acc[mt][nt][2], acc[mt][nt][3]);
        }
    }
}

// ---------------- fp16 tensor-core causal flash attention (ldmatrix + ex2, occ=2) ----------------
#define APS 36
#define A_PH 0
#define A_PL 4608
#define A_KV 9216
#define KV_KH 0
#define KV_VH 2304
#define KV_STAGE 4608
#define A_MSK (A_KV + 2*KV_STAGE)
#define SMEM_ATTN_U32 (A_MSK + S_)

__device__ __forceinline__ void attn_stage_load(
    uint32_t* sma, int st, const uint32_t* kh, const uint32_t* vh, int kt, int tid)
{
    uint32_t* base = sma + A_KV + st * KV_STAGE;
    const int r = tid >> 2, c = tid & 3;
    const size_t gk = (size_t)(kt * 64 + r) * 32;
    cp16(&base[KV_KH + r * APS + c * 4],       kh + gk + c * 4);
    cp16(&base[KV_KH + r * APS + (c + 4) * 4], kh + gk + (c + 4) * 4);
    const size_t gv = (size_t)r * (S_/2) + kt * 32;
    cp16(&base[KV_VH + r * APS + c * 4],       vh + gv + c * 4);
    cp16(&base[KV_VH + r * APS + (c + 4) * 4], vh + gv + (c + 4) * 4);
}

__global__ __launch_bounds__(256, 2) void attn_tc_kernel(const int* __restrict__ amask) {
    extern __shared__ uint32_t sma[];
    uint32_t* sPh = sma + A_PH;
    uint32_t* sPl = sma + A_PL;
    float* sMf = (float*)(sma + A_MSK);

    const int tid  = threadIdx.x;
    const int warp = tid >> 5;
    const int lane = tid & 31;
    const int g = lane >> 2;
    const int t = lane & 3;
    // LPT ordering: heaviest q-tiles first
    const int qtile = (S_ / 128 - 1) - (int)(blockIdx.x >> 5);
    const int bh    = blockIdx.x & 31;
    const int b  = bh >> 4;
    const int h  = bh & 15;
    const int qbase = qtile * 128;
    const int wrow  = warp * 16;

    const int r8 = lane & 7;
    const int aR = ((lane >> 3) & 1) * 8 + r8;
    const int aC = ((lane >> 4) & 1) * 4;
    const int bR = ((lane >> 4) & 1) * 8 + r8;
    const int bC = ((lane >> 3) & 1) * 4;
    const uint32_t smB = (uint32_t)__cvta_generic_to_shared(sma);

    const uint32_t* kh = g_khi + (size_t)bh * S_ * 32;
    const uint32_t* vh = g_vthi + (size_t)bh * HD * (S_/2);

    const int nkt = (qbase + 128) / 64;

    attn_stage_load(sma, 0, kh, vh, 0, tid);
    cp_commit();

    {
        const uint32_t* qgh = g_qhi + ((size_t)bh * S_ + qbase) * 32;
        const uint32_t* qgl = g_qlo + ((size_t)bh * S_ + qbase) * 32;
        for (int idx = tid; idx < 1024; idx += 256) {
            int r = idx >> 3, c4 = (idx & 7) * 4;
            *(uint4*)&sPh[r * APS + c4] = *(const uint4*)(qgh + r * 32 + c4);
            *(uint4*)&sPl[r * APS + c4] = *(const uint4*)(qgl + r * 32 + c4);
        }
        for (int idx = tid; idx < S_; idx += 256)
            sMf[idx] = (amask[b * S_ + idx] == 0) ? -INFINITY : 0.f;
    }
    __syncthreads();

    uint32_t Qh[4][4], Ql[4][4];
    #pragma unroll
    for (int ks = 0; ks < 4; ks++) {
        const uint32_t qaddr = smB + (((wrow + aR) * APS + ks * 8 + aC) << 2);
        ldsm4(Qh[ks], qaddr);
        ldsm4(Ql[ks], qaddr + A_PL * 4);
    }
    // each warp reads/writes only its own 16 sP rows from here on

    float oacc[8][4];
    #pragma unroll
    for (int nt = 0; nt < 8; nt++)
        #pragma unroll
        for (int r = 0; r < 4; r++) oacc[nt][r] = 0.f;
    float mrun[2] = {-INFINITY, -INFINITY};
    float lrun[2] = {0.f, 0.f};

    for (int kt = 0; kt < nkt; kt++) {
        if (kt + 1 < nkt) {
            attn_stage_load(sma, (kt + 1) & 1, kh, vh, kt + 1, tid);
            cp_commit();
            cp_wait<1>();
        } else {
            cp_wait<0>();
        }
        __syncthreads();

        if (kt * 64 <= qbase + wrow + 15) {
            const uint32_t kvB = smB + ((A_KV + (kt & 1) * KV_STAGE) << 2);

            // ---- S = Q K^T ----
            float sacc[8][4];
            #pragma unroll
            for (int nt = 0; nt < 8; nt++)
                #pragma unroll
                for (int r = 0; r < 4; r++) sacc[nt][r] = 0.f;

            #pragma unroll
            for (int ks = 0; ks < 4; ks++) {
                #pragma unroll
                for (int ntp = 0; ntp < 4; ntp++) {
                    uint32_t bb[4];
                    ldsm4(bb, kvB + ((KV_KH + (ntp * 16 + bR) * APS + ks * 8 + bC) << 2));
                    mma_f16(sacc[2 * ntp],     Qh[ks], bb);
                    mma_f16(sacc[2 * ntp],     Ql[ks], bb);
                    mma_f16(sacc[2 * ntp + 1], Qh[ks], bb + 2);
                    mma_f16(sacc[2 * ntp + 1], Ql[ks], bb + 2);
                }
            }

            // ---- masks + row max (log2 domain) ----
            const bool diag = (kt * 64 + 63) > (qbase + wrow);
            float tmax[2] = {-INFINITY, -INFINITY};
            #pragma unroll
            for (int nt = 0; nt < 8; nt++) {
                #pragma unroll
                for (int e = 0; e < 4; e++) {
                    const int colL = nt * 8 + t * 2 + (e & 1);
                    float v = sacc[nt][e] + sMf[kt * 64 + colL];
                    if (diag) {
                        const int row = qbase + wrow + g + ((e >> 1) << 3);
                        const int col = kt * 64 + colL;
                        if (col > row) v = -INFINITY;
                    }
                    sacc[nt][e] = v;
                    tmax[e >> 1] = fmaxf(tmax[e >> 1], v);
                }
            }
            #pragma unroll
            for (int i = 0; i < 2; i++) {
                tmax[i] = fmaxf(tmax[i], __shfl_xor_sync(0xffffffff, tmax[i], 1));
                tmax[i] = fmaxf(tmax[i], __shfl_xor_sync(0xffffffff, tmax[i], 2));
            }

            // ---- online softmax (base-2) ----
            float corr[2], psum[2] = {0.f, 0.f};
            #pragma unroll
            for (int i = 0; i < 2; i++) {
                float mnew = fmaxf(mrun[i], tmax[i]);
                corr[i] = fexp2(mrun[i] - mnew);
                mrun[i] = mnew;
                lrun[i] *= corr[i];
            }
            #pragma unroll
            for (int nt = 0; nt < 8; nt++) {
                oacc[nt][0] *= corr[0]; oacc[nt][1] *= corr[0];
                oacc[nt][2] *= corr[1]; oacc[nt][3] *= corr[1];
            }
            #pragma unroll
            for (int nt = 0; nt < 8; nt++) {
                #pragma unroll
                for (int half = 0; half < 2; half++) {
                    float p0 = fexp2(sacc[nt][half * 2 + 0] - mrun[half]);
                    float p1 = fexp2(sacc[nt][half * 2 + 1] - mrun[half]);
                    psum[half] += p0 + p1;
                    float h0 = hhi(p0), h1 = hhi(p1);
                    const int row = wrow + g + half * 8;
                    sPh[row * APS + nt * 4 + t] = packh(h0, h1);
                    sPl[row * APS + nt * 4 + t] = packh(p0 - h0, p1 - h1);
                }
            }
            #pragma unroll
            for (int i = 0; i < 2; i++) {
                psum[i] += __shfl_xor_sync(0xffffffff, psum[i], 1);
                psum[i] += __shfl_xor_sync(0xffffffff, psum[i], 2);
                lrun[i] += psum[i];
            }
            __syncwarp();

            // ---- O += P V ----
            #pragma unroll
            for (int ks = 0; ks < 4; ks++) {
                uint32_t ph4[4], pl4[4];
                const uint32_t paddr = smB + (((wrow + aR) * APS + ks * 8 + aC) << 2);
                ldsm4(ph4, paddr);
                ldsm4(pl4, paddr + A_PL * 4);
                #pragma unroll
                for (int ntp = 0; ntp < 4; ntp++) {
                    uint32_t vv[4];
                    ldsm4(vv, kvB + ((KV_VH + (ntp * 16 + bR) * APS + ks * 8 + bC) << 2));
                    mma_f16(oacc[2 * ntp],     ph4, vv);
                    mma_f16(oacc[2 * ntp],     pl4, vv);
                    mma_f16(oacc[2 * ntp + 1], ph4, vv + 2);
                    mma_f16(oacc[2 * ntp + 1], pl4, vv + 2);
                }
            }
            __syncwarp();
        }
        __syncthreads();
    }

    // ---- epilogue: o/l, fp16 split, packed write ----
    const float inv0 = 1.f / lrun[0];
    const float inv1 = 1.f / lrun[1];
    const int r0 = qbase + wrow + g;
    const int r1 = r0 + 8;
    #pragma unroll
    for (int nt = 0; nt < 8; nt++) {
        float v0 = oacc[nt][0] * inv0, v1 = oacc[nt][1] * inv0;
        float v2 = oacc[nt][2] * inv1, v3 = oacc[nt][3] * inv1;
        const size_t o0 = (size_t)(b * S_ + r0) * 512 + h * 32 + nt * 4 + t;
        const size_t o1 = (size_t)(b * S_ + r1) * 512 + h * 32 + nt * 4 + t;
        float h0 = hhi(v0), h1 = hhi(v1), h2 = hhi(v2), h3 = hhi(v3);
        g_yhi[o0] = packh(h0, h1);
        g_ylo[o0] = packh(v0 - h0, v1 - h1);
        g_yhi[o1] = packh(h2, h3);
        g_ylo[o1] = packh(v2 - h2, v3 - h3);
    }
}

// ---------------- launch ----------------
extern "C" void kernel_launch(void* const* d_in, const int* in_sizes, int n_in,
                              void* d_out, int out_size)
{
    const float* x     = (const float*)d_in[0];
    const float* w_qkv = (const float*)d_in[1];
    const float* w_o   = (const float*)d_in[2];
    const int*   amask = (const int*)d_in[3];
    float* out = (float*)d_out;

    float* qkv_p;
    uint32_t *xhi, *xlo, *wqh, *woh, *yhi, *ylo;
    cudaGetSymbolAddress((void**)&qkv_p, g_qkv);
    cudaGetSymbolAddress((void**)&xhi, g_xhi);
    cudaGetSymbolAddress((void**)&xlo, g_xlo);
    cudaGetSymbolAddress((void**)&wqh, g_wqh);
    cudaGetSymbolAddress((void**)&woh, g_woh);
    cudaGetSymbolAddress((void**)&yhi, g_yhi);
    cudaGetSymbolAddress((void**)&ylo, g_ylo);

    const int smem_gemm = SMEM_GEMM_U32 * 4;
    cudaFuncSetAttribute(f16_gemm_kernel,
                         cudaFuncAttributeMaxDynamicSharedMemorySize, smem_gemm);
    const int smem_attn = SMEM_ATTN_U32 * 4;
    cudaFuncSetAttribute(attn_tc_kernel,
                         cudaFuncAttributeMaxDynamicSharedMemorySize, smem_attn);

    rope_table_kernel<<<256, 256>>>();

    split2_kernel<<<(B_*S_*D_/2 + 255) / 256, 256>>>(x, xhi, xlo, B_*S_*D_/2);
    wsplit_t_kernel<<<dim3(3*D_/32, D_/32), 256>>>(w_qkv, wqh, D_, 3*D_);
    wsplit_t_kernel<<<dim3(D_/32, D_/32), 256>>>(w_o, woh, D_, D_);

    // QKV = x @ w_qkv
    f16_gemm_kernel<<<dim3(3*D_/128, B_*S_/128), 256, smem_gemm>>>(
        xhi, xlo, wqh, qkv_p, B_*S_, 3*D_, D_);

    rope_split_kernel<<<B_*H_*(S_/32), 256>>>();

    attn_tc_kernel<<<(S_/128) * B_ * H_, 256, smem_attn>>>(amask);

    // out = y @ w_o
    f16_gemm_kernel<<<dim3(D_/128, B_*S_/128), 256, smem_gemm>>>(
        yhi, ylo, woh, out, B_*S_, D_, D_);
}